// round 6
// baseline (speedup 1.0000x reference)
#include <cuda_runtime.h>
#include <math.h>
#include <stdint.h>

// Shapes fixed: B=64, S=512, H=1024, M=26, E=676
// out: logits(64,2) ++ node_logits(64,26,2) ++ edge_logits(64,676,2) = 89984 f32
//
// GEMMs via mma.m16n8k32.s8, fixed-point split q = h*128 + l (15-bit),
// per-row A scale + per-col B scale (exact factoring), 3 IMMA -> 2 acc planes:
//  G1: clsPad(128x1024) @ [W_naf|W_cd](1024x2048)       -> g_C2 (tanh cols>=1024)
//  G2: nodeC(Rx1024)    @ [W_nd|W1+W3|W2-W3](1024x3072) -> g_Cbig (tanh cols<1024)

// ---------------- scratch ----------------
__device__ float g_bcat2[2048];
__device__ float g_bcat3[3072];
__device__ float g_node[64 * 26 * 1024];
__device__ float g_C2[64 * 2048];
__device__ float g_Cbig[1664 * 3072];
__device__ int   g_count[64];
__device__ int   g_pref[64];
__device__ int   g_rowmap[1664];
__device__ int   g_R;
__device__ int   g_M1 = 64;
__device__ float g_zlog[2];
__device__ float g_saN[1664], g_saC[128], g_sbN[3072], g_sbC[2048];

// int8 fragment packs. Per (mb|nb, slab K=64): A 16KB (hi 8K | lo 8K), B 16KB (hi/lo interleaved)
__device__ __align__(16) uint8_t g_ApackN[13 * 16 * 16384];
__device__ __align__(16) uint8_t g_ApackC[1 * 16 * 16384];
__device__ __align__(16) uint8_t g_BpackN[24 * 16 * 16384];
__device__ __align__(16) uint8_t g_BpackC[16 * 16 * 16384];

// ---------------- helpers ----------------
__device__ __forceinline__ uint32_t smem_u32(const void* p) {
    uint32_t a;
    asm("{ .reg .u64 t; cvta.to.shared.u64 t, %1; cvt.u32.u64 %0, t; }" : "=r"(a) : "l"(p));
    return a;
}
#define CP16(dst, src) asm volatile("cp.async.cg.shared.global [%0], [%1], 16;" :: "r"(dst), "l"(src) : "memory")
#define CP_COMMIT()    asm volatile("cp.async.commit_group;" ::: "memory")
#define CP_WAIT1()     asm volatile("cp.async.wait_group 1;" ::: "memory")
#define CP_WAIT0()     asm volatile("cp.async.wait_group 0;" ::: "memory")

#define IMMA(d, a, b0_, b1_) \
    asm volatile("mma.sync.aligned.m16n8k32.row.col.s32.s8.s8.s32 " \
                 "{%0,%1,%2,%3}, {%4,%5,%6,%7}, {%8,%9}, {%0,%1,%2,%3};" \
                 : "+r"((d)[0]), "+r"((d)[1]), "+r"((d)[2]), "+r"((d)[3]) \
                 : "r"((a).x), "r"((a).y), "r"((a).z), "r"((a).w), "r"(b0_), "r"(b1_))

// split q = h*128 + l (h in [-127,127], l in [-64,63]); pack 4 to hi/lo words
__device__ __forceinline__ uint32_t packhl(int q0, int q1, int q2, int q3, uint32_t& lo) {
    int h0 = (q0 + 64) >> 7, h1 = (q1 + 64) >> 7, h2 = (q2 + 64) >> 7, h3 = (q3 + 64) >> 7;
    int l0 = q0 - (h0 << 7), l1 = q1 - (h1 << 7), l2 = q2 - (h2 << 7), l3 = q3 - (h3 << 7);
    lo = (uint32_t)(l0 & 255) | ((uint32_t)(l1 & 255) << 8) |
         ((uint32_t)(l2 & 255) << 16) | ((uint32_t)(l3 & 255) << 24);
    return (uint32_t)(h0 & 255) | ((uint32_t)(h1 & 255) << 8) |
           ((uint32_t)(h2 & 255) << 16) | ((uint32_t)(h3 & 255) << 24);
}

// ---------------- bias / zlog ----------------
__global__ void prep_bias_kernel(const float* __restrict__ b_naf, const float* __restrict__ b_cd,
                                 const float* __restrict__ b_nd,  const float* __restrict__ b_ed)
{
    int t = blockIdx.x * blockDim.x + threadIdx.x;
    if (t < 2048) g_bcat2[t] = (t < 1024) ? b_naf[t] : b_cd[t - 1024];
    if (t < 3072) g_bcat3[t] = (t < 1024) ? b_nd[t] : ((t < 2048) ? b_ed[t - 1024] : 0.0f);
}

__global__ void zlog_kernel(const float* __restrict__ b_nd, const float* __restrict__ W_no,
                            const float* __restrict__ b_no)
{
    int tid = threadIdx.x;  // 128
    float a0 = 0.f, a1 = 0.f;
#pragma unroll
    for (int hh = 0; hh < 8; hh++) {
        float x = tanhf(b_nd[tid * 8 + hh]);
        a0 = fmaf(x, W_no[(tid * 8 + hh) * 2],     a0);
        a1 = fmaf(x, W_no[(tid * 8 + hh) * 2 + 1], a1);
    }
#pragma unroll
    for (int o = 16; o > 0; o >>= 1) {
        a0 += __shfl_down_sync(0xffffffffu, a0, o);
        a1 += __shfl_down_sync(0xffffffffu, a1, o);
    }
    __shared__ float s0[4], s1[4];
    int wid = tid >> 5, lane = tid & 31;
    if (lane == 0) { s0[wid] = a0; s1[wid] = a1; }
    __syncthreads();
    if (tid == 0) {
        g_zlog[0] = s0[0] + s0[1] + s0[2] + s0[3] + b_no[0];
        g_zlog[1] = s1[0] + s1[1] + s1[2] + s1[3] + b_no[1];
    }
}

// ---------------- segment means + counts ----------------
__global__ void seg_kernel(const float* __restrict__ seq, const int* __restrict__ off)
{
    int b = blockIdx.x, m = blockIdx.y;
    __shared__ int soff[25];
    int tid = threadIdx.x;
    if (tid < 25) soff[tid] = off[b * 25 + tid];
    __syncthreads();
    int c = 0;
#pragma unroll
    for (int q = 0; q < 25; q++) c += (soff[q] > 0);
    if (m == 0 && tid == 0) g_count[b] = c;

    float* dst = g_node + ((size_t)b * 26 + m) * 1024 + tid * 4;
    if (m >= c) { float4 z = {0.f, 0.f, 0.f, 0.f}; *(float4*)dst = z; return; }
    int e  = soff[m];
    int s0 = (m ? soff[m - 1] : 0) + 1;
    int len = e - s0 + 1;
    const float* p = seq + ((size_t)b * 512 + s0) * 1024 + tid * 4;
    float4 acc = {0.f, 0.f, 0.f, 0.f};
#pragma unroll 4
    for (int s = 0; s < len; s++) {
        float4 v = *(const float4*)(p + (size_t)s * 1024);
        acc.x += v.x; acc.y += v.y; acc.z += v.z; acc.w += v.w;
    }
    float inv = 1.0f / (float)len;
    float4 r = {acc.x * inv, acc.y * inv, acc.z * inv, acc.w * inv};
    *(float4*)dst = r;
}

// ---------------- prefix + rowmap ----------------
__global__ void prefix_kernel()
{
    __shared__ int sc[64], sp[64];
    int tid = threadIdx.x;
    if (tid < 64) sc[tid] = g_count[tid];
    __syncthreads();
    if (tid == 0) {
        int p = 0;
        for (int b = 0; b < 64; b++) { sp[b] = p; g_pref[b] = p; p += sc[b] + 1; }
        g_R = p;
    }
    __syncthreads();
    for (int r = tid; r < 1664; r += 256) {
        int b = r / 26, m = r - b * 26;
        if (m <= sc[b]) g_rowmap[sp[b] + m] = r;
    }
}

// ---------------- node_full[b,count[b],:] += naf ----------------
__global__ void scatter_naf_kernel()
{
    int b = blockIdx.x, tid = threadIdx.x;
    int c = g_count[b];
    float* dst = g_node + ((size_t)b * 26 + c) * 1024 + tid * 4;
    const float* naf = g_C2 + (size_t)b * 2048 + tid * 4;
    float4 d = *(float4*)dst;
    float4 n = *(const float4*)naf;
    d.x += n.x; d.y += n.y; d.z += n.z; d.w += n.w;
    *(float4*)dst = d;
}

// ---------------- B pack (8 cols x full K per block; max -> quantize) ----------------
__device__ __forceinline__ float wval(int k, int n, const float* __restrict__ Wa,
                                      const float* __restrict__ Wb, int which)
{
    if (which == 0) return (n < 1024) ? Wa[k * 1024 + n] : Wb[k * 1024 + (n - 1024)];
    if (n < 1024) return Wa[k * 1024 + n];
    if (n < 2048) { int c = n - 1024; return Wb[k * 1024 + c] + Wb[(2048 + k) * 1024 + c]; }
    int c = n - 2048;
    return Wb[(1024 + k) * 1024 + c] - Wb[(2048 + k) * 1024 + c];
}

__device__ void packB_region(int nb, int n8, const float* __restrict__ Wa,
                             const float* __restrict__ Wb, int which,
                             uint8_t* __restrict__ Bpack, float* __restrict__ sbv)
{
    __shared__ float cmax[8][33];
    __shared__ float srs[8];
    int tid = threadIdx.x;
    {
        int c8 = tid & 7, kch = tid >> 3;   // 8 cols x 32 k-chunks
        int colg = nb * 128 + n8 * 8 + c8;
        float mx = 0.f;
        for (int kk = 0; kk < 32; kk++)
            mx = fmaxf(mx, fabsf(wval(kch * 32 + kk, colg, Wa, Wb, which)));
        cmax[c8][kch] = mx;
    }
    __syncthreads();
    if (tid < 8) {
        float m = 0.f;
        for (int q = 0; q < 32; q++) m = fmaxf(m, cmax[tid][q]);
        srs[tid] = (m > 0.f) ? 16256.0f / m : 0.f;
        sbv[nb * 128 + n8 * 8 + tid] = (m > 0.f) ? m / 16256.0f : 0.f;
    }
    __syncthreads();
    int lane = tid & 31, kgrp = tid >> 5;
    int gq = lane >> 2, tg = lane & 3;
    int col = nb * 128 + n8 * 8 + gq;
    float rs = srs[gq];
#pragma unroll
    for (int i = 0; i < 4; i++) {
        int ks = kgrp * 4 + i;               // k32 group 0..31
        int k0 = ks * 32 + tg * 4;
        int q0[4], q1[4];
#pragma unroll
        for (int e = 0; e < 4; e++) {
            q0[e] = __float2int_rn(wval(k0 + e,      col, Wa, Wb, which) * rs);
            q1[e] = __float2int_rn(wval(k0 + 16 + e, col, Wa, Wb, which) * rs);
        }
        uint32_t lo0, lo1;
        uint32_t hi0 = packhl(q0[0], q0[1], q0[2], q0[3], lo0);
        uint32_t hi1 = packhl(q1[0], q1[1], q1[2], q1[3], lo1);
        int s = ks >> 1, ks2 = ks & 1;
        *(uint4*)(Bpack + ((size_t)(nb * 16 + s)) * 16384 + (ks2 * 16 + n8) * 512 + lane * 16)
            = make_uint4(hi0, hi1, lo0, lo1);
    }
}

__global__ void packB3_kernel(const float* __restrict__ W_nd, const float* __restrict__ W_ed)
{ packB_region(blockIdx.x, blockIdx.y, W_nd, W_ed, 1, g_BpackN, g_sbN); }
__global__ void packB2_kernel(const float* __restrict__ W_naf, const float* __restrict__ W_cd)
{ packB_region(blockIdx.x, blockIdx.y, W_naf, W_cd, 0, g_BpackC, g_sbC); }

// ---------------- A pack (16 rows x full K per block) ----------------
// which=0: node compact rows via rowmap (R=g_R). which=1: cls rows (R=64), pad 128.
__device__ void packA_region(int gm, int which, const float* __restrict__ seq)
{
    __shared__ float rmax[16][17];
    __shared__ float srs[16];
    __shared__ int   srow[16];
    int tid = threadIdx.x;
    int R = (which == 0) ? g_R : 64;
    if (tid < 16) {
        int r = gm * 16 + tid;
        srow[tid] = (r < R) ? ((which == 0) ? g_rowmap[r] : r) : -1;
    }
    __syncthreads();
    {
        int r16 = tid & 15, kch = tid >> 4;   // 16 rows x 16 k-chunks of 64
        int src = srow[r16];
        float mx = 0.f;
        if (src >= 0) {
            const float* p = (which == 0) ? (g_node + (size_t)src * 1024)
                                          : (seq + (size_t)src * 524288);
            for (int kk = 0; kk < 64; kk++) mx = fmaxf(mx, fabsf(p[kch * 64 + kk]));
        }
        rmax[r16][kch] = mx;
    }
    __syncthreads();
    if (tid < 16) {
        float m = 0.f;
        for (int q = 0; q < 16; q++) m = fmaxf(m, rmax[tid][q]);
        srs[tid] = (m > 0.f) ? 16256.0f / m : 0.f;
        int r = gm * 16 + tid;
        float sv = (m > 0.f) ? m / 16256.0f : 0.f;
        if (which == 0) { if (r < 1664) g_saN[r] = sv; }
        else            { if (r < 128)  g_saC[r] = sv; }
    }
    __syncthreads();
    int lane = tid & 31, kgrp = tid >> 5;
    int gq = lane >> 2, tg = lane & 3;
    int mb = gm >> 3, mt16 = gm & 7;
    uint8_t* Apack = (which == 0) ? g_ApackN : g_ApackC;
    int s0 = srow[gq], s1 = srow[gq + 8];
    float rs0 = srs[gq], rs1 = srs[gq + 8];
    const float* p0 = (s0 >= 0) ? ((which == 0) ? g_node + (size_t)s0 * 1024
                                                : seq + (size_t)s0 * 524288) : 0;
    const float* p1 = (s1 >= 0) ? ((which == 0) ? g_node + (size_t)s1 * 1024
                                                : seq + (size_t)s1 * 524288) : 0;
#pragma unroll
    for (int i = 0; i < 4; i++) {
        int ks = kgrp * 4 + i;
        int k0 = ks * 32 + tg * 4;
        int qa[4][4];
#pragma unroll
        for (int e = 0; e < 4; e++) {
            qa[0][e] = p0 ? __float2int_rn(p0[k0 + e]      * rs0) : 0;   // a0 row gq
            qa[1][e] = p1 ? __float2int_rn(p1[k0 + e]      * rs1) : 0;   // a1 row gq+8
            qa[2][e] = p0 ? __float2int_rn(p0[k0 + 16 + e] * rs0) : 0;   // a2 row gq  k+16
            qa[3][e] = p1 ? __float2int_rn(p1[k0 + 16 + e] * rs1) : 0;   // a3 row gq+8 k+16
        }
        uint32_t hi[4], lo[4];
#pragma unroll
        for (int f = 0; f < 4; f++) hi[f] = packhl(qa[f][0], qa[f][1], qa[f][2], qa[f][3], lo[f]);
        int s = ks >> 1, ks2 = ks & 1;
        size_t base = ((size_t)(mb * 16 + s)) * 16384 + (ks2 * 8 + mt16) * 512 + lane * 16;
        *(uint4*)(Apack + base)        = make_uint4(hi[0], hi[1], hi[2], hi[3]);
        *(uint4*)(Apack + base + 8192) = make_uint4(lo[0], lo[1], lo[2], lo[3]);
    }
}

__global__ void packAnode_kernel() { packA_region(blockIdx.x, 0, 0); }
__global__ void packAcls_kernel(const float* __restrict__ seq) { packA_region(blockIdx.x, 1, seq); }

// ---------------- IMMA GEMM: block 128x128, K slabs of 64, 16 slabs ----------------
__global__ __launch_bounds__(256) void imma_gemm(
    const uint8_t* __restrict__ Apack, const uint8_t* __restrict__ Bpack,
    const float* __restrict__ sa, const float* __restrict__ sbv,
    const float* __restrict__ bias, float* __restrict__ C, int ldc,
    const int* __restrict__ Mptr, int tanh_lo, int tanh_hi)
{
    int R = *Mptr;
    int mb = blockIdx.x, nb = blockIdx.y;
    if (mb * 128 >= R) return;
    extern __shared__ char smbuf[];
    uint32_t sbs = smem_u32(smbuf);
    int tid = threadIdx.x, lane = tid & 31, w = tid >> 5;
    int gq = lane >> 2, tg = lane & 3;
    int wn8 = (w >> 1) * 4;                 // warp 8-col group base
    const uint8_t* Ab = Apack + (size_t)(mb * 16) * 16384;
    const uint8_t* Bb = Bpack + (size_t)(nb * 16) * 16384;

    int acc1[4][4][4], acc2[4][4][4];
#pragma unroll
    for (int mt = 0; mt < 4; mt++)
#pragma unroll
        for (int nt = 0; nt < 4; nt++)
#pragma unroll
            for (int q = 0; q < 4; q++) { acc1[mt][nt][q] = 0; acc2[mt][nt][q] = 0; }

    {   // stage 0
        uint32_t d = sbs;
#pragma unroll
        for (int i = 0; i < 4; i++) CP16(d + i * 4096 + tid * 16, Ab + i * 4096 + tid * 16);
#pragma unroll
        for (int i = 0; i < 4; i++) CP16(d + 16384 + i * 4096 + tid * 16, Bb + i * 4096 + tid * 16);
        CP_COMMIT();
    }
    for (int s = 0; s < 16; s++) {
        if (s < 15) {
            uint32_t d = sbs + ((s + 1) & 1) * 32768;
            const uint8_t* A1 = Ab + (size_t)(s + 1) * 16384;
            const uint8_t* B1 = Bb + (size_t)(s + 1) * 16384;
#pragma unroll
            for (int i = 0; i < 4; i++) CP16(d + i * 4096 + tid * 16, A1 + i * 4096 + tid * 16);
#pragma unroll
            for (int i = 0; i < 4; i++) CP16(d + 16384 + i * 4096 + tid * 16, B1 + i * 4096 + tid * 16);
            CP_COMMIT();
            CP_WAIT1();
        } else {
            CP_WAIT0();
        }
        __syncthreads();
        const char* st = smbuf + (s & 1) * 32768;
#pragma unroll
        for (int ks2 = 0; ks2 < 2; ks2++) {
            uint4 Ah[4], Al[4];
#pragma unroll
            for (int mt = 0; mt < 4; mt++) {
                uint32_t ao = (uint32_t)(ks2 * 8 + (w & 1) * 4 + mt) * 512 + lane * 16;
                Ah[mt] = *(const uint4*)(st + ao);
                Al[mt] = *(const uint4*)(st + 8192 + ao);
            }
#pragma unroll
            for (int nt = 0; nt < 4; nt++) {
                uint32_t bo = 16384u + (uint32_t)(ks2 * 16 + wn8 + nt) * 512 + lane * 16;
                uint4 bf = *(const uint4*)(st + bo);
#pragma unroll
                for (int mt = 0; mt < 4; mt++) IMMA(acc1[mt][nt], Ah[mt], bf.x, bf.y);
#pragma unroll
                for (int mt = 0; mt < 4; mt++) IMMA(acc2[mt][nt], Al[mt], bf.x, bf.y);
#pragma unroll
                for (int mt = 0; mt < 4; mt++) IMMA(acc2[mt][nt], Ah[mt], bf.z, bf.w);
            }
        }
        __syncthreads();
    }

    // epilogue: v = (acc1*16384 + acc2*128)*sa*sb + bias, optional tanh
#pragma unroll
    for (int nt = 0; nt < 4; nt++) {
        int col = nb * 128 + (w >> 1) * 32 + nt * 8 + 2 * tg;
        float sb0 = sbv[col], sb1 = sbv[col + 1];
        float bi0 = bias[col], bi1 = bias[col + 1];
        bool dt = (col >= tanh_lo) && (col < tanh_hi);
#pragma unroll
        for (int mt = 0; mt < 4; mt++) {
            int r0 = mb * 128 + (w & 1) * 64 + mt * 16 + gq;
            int r1 = r0 + 8;
            float sa0 = sa[r0], sa1 = sa[r1];
            float v00 = ((float)acc1[mt][nt][0] * 16384.f + (float)acc2[mt][nt][0] * 128.f) * (sa0 * sb0) + bi0;
            float v01 = ((float)acc1[mt][nt][1] * 16384.f + (float)acc2[mt][nt][1] * 128.f) * (sa0 * sb1) + bi1;
            float v10 = ((float)acc1[mt][nt][2] * 16384.f + (float)acc2[mt][nt][2] * 128.f) * (sa1 * sb0) + bi0;
            float v11 = ((float)acc1[mt][nt][3] * 16384.f + (float)acc2[mt][nt][3] * 128.f) * (sa1 * sb1) + bi1;
            if (dt) { v00 = tanhf(v00); v01 = tanhf(v01); v10 = tanhf(v10); v11 = tanhf(v11); }
            if (r0 < R) { float2 p = {v00, v01}; *(float2*)(C + (size_t)r0 * ldc + col) = p; }
            if (r1 < R) { float2 p = {v10, v11}; *(float2*)(C + (size_t)r1 * ldc + col) = p; }
        }
    }
}

// ---------------- heads ----------------
__global__ void head_kernel(const float* __restrict__ W_co, const float* __restrict__ b_co,
                            const float* __restrict__ W_no, const float* __restrict__ b_no,
                            float* __restrict__ out)
{
    int blk = blockIdx.x, tid = threadIdx.x;   // 128 threads
    const float* x; const float* Wv; const float* bs; float* op;
    if (blk < 64) {
        x  = g_C2 + (size_t)blk * 2048 + 1024;
        Wv = W_co; bs = b_co; op = out + blk * 2;
    } else {
        int r = blk - 64;
        int b = r / 26, m = r - b * 26;
        op = out + 128 + r * 2;
        if (m > g_count[b]) {
            if (tid == 0) { op[0] = g_zlog[0]; op[1] = g_zlog[1]; }
            return;
        }
        x  = g_Cbig + (size_t)(g_pref[b] + m) * 3072;
        Wv = W_no; bs = b_no;
    }
    float xs[8], ws[16];
    {
        const float4* xv = (const float4*)(x + tid * 8);
        *(float4*)xs       = xv[0];
        *(float4*)(xs + 4) = xv[1];
        const float4* wv = (const float4*)(Wv + tid * 16);
#pragma unroll
        for (int q = 0; q < 4; q++) *(float4*)(ws + q * 4) = wv[q];
    }
    float a0 = 0.f, a1 = 0.f;
#pragma unroll
    for (int hh = 0; hh < 8; hh++) {
        a0 = fmaf(xs[hh], ws[2 * hh], a0);
        a1 = fmaf(xs[hh], ws[2 * hh + 1], a1);
    }
#pragma unroll
    for (int o = 16; o > 0; o >>= 1) {
        a0 += __shfl_down_sync(0xffffffffu, a0, o);
        a1 += __shfl_down_sync(0xffffffffu, a1, o);
    }
    __shared__ float s0[4], s1[4];
    int wid = tid >> 5, lane = tid & 31;
    if (lane == 0) { s0[wid] = a0; s1[wid] = a1; }
    __syncthreads();
    if (tid == 0) {
        op[0] = s0[0] + s0[1] + s0[2] + s0[3] + bs[0];
        op[1] = s1[0] + s1[1] + s1[2] + s1[3] + bs[1];
    }
}

// ---------------- edge logits ----------------
__global__ void edge_kernel(const float* __restrict__ W_eo, const float* __restrict__ b_eo,
                            const float* __restrict__ b_ed, float* __restrict__ out)
{
    int ke = blockIdx.x;
    int b  = ke / 676;
    int k  = ke - b * 676;
    int n  = g_count[b] + 1;
    int tid = threadIdx.x;   // 128

    float xs[8];
    if (k < n * n) {
        int i = k / n, j = k - i * n;
        int pj = g_pref[b] + j, pi = g_pref[b] + i;
        const float* U = g_Cbig + (size_t)pj * 3072 + 1024 + tid * 8;
        const float* V = g_Cbig + (size_t)pi * 3072 + 2048 + tid * 8;
        float us[8], vs[8];
        *(float4*)us       = ((const float4*)U)[0];
        *(float4*)(us + 4) = ((const float4*)U)[1];
        *(float4*)vs       = ((const float4*)V)[0];
        *(float4*)(vs + 4) = ((const float4*)V)[1];
#pragma unroll
        for (int hh = 0; hh < 8; hh++) xs[hh] = tanhf(us[hh] + vs[hh]);
    } else {
        const float* be = b_ed + tid * 8;
        float bs8[8];
        *(float4*)bs8       = ((const float4*)be)[0];
        *(float4*)(bs8 + 4) = ((const float4*)be)[1];
#pragma unroll
        for (int hh = 0; hh < 8; hh++) xs[hh] = tanhf(bs8[hh]);
    }
    float ws[16];
    {
        const float4* wv = (const float4*)(W_eo + tid * 16);
#pragma unroll
        for (int q = 0; q < 4; q++) *(float4*)(ws + q * 4) = wv[q];
    }
    float a0 = 0.f, a1 = 0.f;
#pragma unroll
    for (int hh = 0; hh < 8; hh++) {
        a0 = fmaf(xs[hh], ws[2 * hh], a0);
        a1 = fmaf(xs[hh], ws[2 * hh + 1], a1);
    }
#pragma unroll
    for (int o = 16; o > 0; o >>= 1) {
        a0 += __shfl_down_sync(0xffffffffu, a0, o);
        a1 += __shfl_down_sync(0xffffffffu, a1, o);
    }
    __shared__ float s0[4], s1[4];
    int wid = tid >> 5, lane = tid & 31;
    if (lane == 0) { s0[wid] = a0; s1[wid] = a1; }
    __syncthreads();
    if (tid == 0) {
        float* op = out + 3456 + (size_t)ke * 2;
        op[0] = s0[0] + s0[1] + s0[2] + s0[3] + b_eo[0];
        op[1] = s1[0] + s1[1] + s1[2] + s1[3] + b_eo[1];
    }
}

// ---------------- launch ----------------
extern "C" void kernel_launch(void* const* d_in, const int* in_sizes, int n_in,
                              void* d_out, int out_size)
{
    const float* seq   = (const float*)d_in[0];
    const int*   off   = (const int*)d_in[1];
    const float* W_naf = (const float*)d_in[4];
    const float* b_naf = (const float*)d_in[5];
    const float* W_cd  = (const float*)d_in[6];
    const float* b_cd  = (const float*)d_in[7];
    const float* W_co  = (const float*)d_in[8];
    const float* b_co  = (const float*)d_in[9];
    const float* W_nd  = (const float*)d_in[10];
    const float* b_nd  = (const float*)d_in[11];
    const float* W_no  = (const float*)d_in[12];
    const float* b_no  = (const float*)d_in[13];
    const float* W_ed  = (const float*)d_in[14];
    const float* b_ed  = (const float*)d_in[15];
    const float* W_eo  = (const float*)d_in[16];
    const float* b_eo  = (const float*)d_in[17];
    float* out = (float*)d_out;

    float *pbcat2, *pbcat3, *pC2, *pCbig, *psaN, *psaC, *psbN, *psbC;
    uint8_t *pApN, *pApC, *pBpN, *pBpC;
    int *pR, *pM1;
    cudaGetSymbolAddress((void**)&pbcat2, g_bcat2);
    cudaGetSymbolAddress((void**)&pbcat3, g_bcat3);
    cudaGetSymbolAddress((void**)&pC2,    g_C2);
    cudaGetSymbolAddress((void**)&pCbig,  g_Cbig);
    cudaGetSymbolAddress((void**)&psaN,   g_saN);
    cudaGetSymbolAddress((void**)&psaC,   g_saC);
    cudaGetSymbolAddress((void**)&psbN,   g_sbN);
    cudaGetSymbolAddress((void**)&psbC,   g_sbC);
    cudaGetSymbolAddress((void**)&pApN,   g_ApackN);
    cudaGetSymbolAddress((void**)&pApC,   g_ApackC);
    cudaGetSymbolAddress((void**)&pBpN,   g_BpackN);
    cudaGetSymbolAddress((void**)&pBpC,   g_BpackC);
    cudaGetSymbolAddress((void**)&pR,     g_R);
    cudaGetSymbolAddress((void**)&pM1,    g_M1);

    cudaFuncSetAttribute(imma_gemm, cudaFuncAttributeMaxDynamicSharedMemorySize, 65536);

    // weight-only prep
    prep_bias_kernel<<<12, 256>>>(b_naf, b_cd, b_nd, b_ed);
    zlog_kernel<<<1, 128>>>(b_nd, W_no, b_no);
    packB3_kernel<<<dim3(24, 16), 256>>>(W_nd, W_ed);
    packB2_kernel<<<dim3(16, 16), 256>>>(W_naf, W_cd);
    // data path
    seg_kernel<<<dim3(64, 26), 256>>>(seq, off);
    prefix_kernel<<<1, 256>>>();
    packAcls_kernel<<<8, 256>>>(seq);
    // G1: clsPad @ [W_naf | W_cd] -> g_C2 (tanh cols [1024,2048))
    imma_gemm<<<dim3(1, 16), 256, 65536>>>(pApC, pBpC, psaC, psbC, pbcat2, pC2, 2048, pM1, 1024, 2048);
    scatter_naf_kernel<<<64, 256>>>();
    packAnode_kernel<<<104, 256>>>();
    // G2: nodeC @ [W_nd | W1+W3 | W2-W3] -> g_Cbig (tanh cols [0,1024))
    imma_gemm<<<dim3(13, 24), 256, 65536>>>(pApN, pBpN, psaN, psbN, pbcat3, pCbig, 3072, pR, 0, 1024);
    // heads
    head_kernel<<<64 + 1664, 128>>>(W_co, b_co, W_no, b_no, out);
    edge_kernel<<<64 * 676, 128>>>(W_eo, b_eo, b_ed, out);
}

// round 7
// speedup vs baseline: 2.2834x; 2.2834x over previous
#include <cuda_runtime.h>
#include <cuda_fp16.h>
#include <math.h>
#include <stdint.h>

// Shapes (fixed): B=64, S=512, H=1024, M=26, E=676
// Output: logits(64,2) ++ node_logits(64,26,2) ++ edge_logits(64,676,2) = 89984 f32
//
// GEMMs via legacy mma.m16n8k16.f16, 3-term hi/lo split; main term f32-acc,
// correction terms (Al*Bh, Ah*Bl) share an f16 accumulator.
//  G1: cls(64x1024)   @ [W_naf|W_cd](1024x2048)          -> g_C2
//  G2: nodeC(Rx1024)  @ [W_nd|W1+W3|W2-W3](1024x3072)    -> g_Cbig (compact rows)
// Block tile 64x128, K slabs of 32, pre-fragmented packs, cp.async double buffer.

// ---------------- scratch ----------------
__device__ float g_bcat2[2048];
__device__ float g_bcat3[3072];
__device__ float g_node[64 * 26 * 1024];
__device__ float g_C2[64 * 2048];
__device__ float g_Cbig[1664 * 3072];    // compact rows used: [T_nd | U | V]
__device__ int   g_count[64];
__device__ int   g_pref[64];
__device__ int   g_rowmap[1664];
__device__ int   g_R;
__device__ int   g_M1 = 64;
__device__ float g_zlog[2];
__device__ float g_elog[2];

// pre-fragmented fp16 hi/lo packs (slab = 128rows x 32k: hi 8KB + lo 8KB)
__device__ __align__(16) __half g_ApackN[13 * 32 * 8192];
__device__ __align__(16) __half g_ApackC[32 * 8192];
__device__ __align__(16) __half g_BpackN[24 * 32 * 8192];
__device__ __align__(16) __half g_BpackC[16 * 32 * 8192];

// ---------------- helpers ----------------
__device__ __forceinline__ uint32_t smem_u32(const void* p) {
    uint32_t a;
    asm("{ .reg .u64 t; cvta.to.shared.u64 t, %1; cvt.u32.u64 %0, t; }" : "=r"(a) : "l"(p));
    return a;
}
#define CP16(dst, src) asm volatile("cp.async.cg.shared.global [%0], [%1], 16;" :: "r"(dst), "l"(src) : "memory")
#define CP_COMMIT()    asm volatile("cp.async.commit_group;" ::: "memory")
#define CP_WAIT1()     asm volatile("cp.async.wait_group 1;" ::: "memory")
#define CP_WAIT0()     asm volatile("cp.async.wait_group 0;" ::: "memory")

// f32-accumulator HMMA
#define MMA16(d, a, bb0, bb1) \
    asm volatile("mma.sync.aligned.m16n8k16.row.col.f32.f16.f16.f32 " \
                 "{%0,%1,%2,%3}, {%4,%5,%6,%7}, {%8,%9}, {%0,%1,%2,%3};" \
                 : "+f"((d)[0]), "+f"((d)[1]), "+f"((d)[2]), "+f"((d)[3]) \
                 : "r"((a).x), "r"((a).y), "r"((a).z), "r"((a).w), "r"(bb0), "r"(bb1))
// f16-accumulator HMMA (corrections)
#define MMA16H(d, a, bb0, bb1) \
    asm volatile("mma.sync.aligned.m16n8k16.row.col.f16.f16.f16.f16 " \
                 "{%0,%1}, {%2,%3,%4,%5}, {%6,%7}, {%0,%1};" \
                 : "+r"((d)[0]), "+r"((d)[1]) \
                 : "r"((a).x), "r"((a).y), "r"((a).z), "r"((a).w), "r"(bb0), "r"(bb1))

// hi/lo fp16 split of a float pair -> packed half2 regs
__device__ __forceinline__ void hl2(float a, float b, uint32_t& h, uint32_t& l) {
    __half ha = __float2half_rn(a), hb = __float2half_rn(b);
    __half la = __float2half_rn(a - __half2float(ha));
    __half lb = __float2half_rn(b - __half2float(hb));
    __half2 H = __halves2half2(ha, hb), L = __halves2half2(la, lb);
    h = *(uint32_t*)&H; l = *(uint32_t*)&L;
}

// fast tanh: 1 - 2/(exp(2x)+1) via ex2.approx + rcp.approx (~1e-6 abs err)
__device__ __forceinline__ float ftanh(float x) {
    float e;
    asm("ex2.approx.f32 %0, %1;" : "=f"(e) : "f"(x * 2.8853900817779268f));
    float r;
    asm("rcp.approx.f32 %0, %1;" : "=f"(r) : "f"(e + 1.0f));
    return fmaf(-2.0f, r, 1.0f);
}

__device__ __forceinline__ float4 ld4(const float* p) { return *(const float4*)p; }

// ---------------- prep: biases + zlog + elog (one launch) ----------------
__device__ void head_const_region(const float* __restrict__ bvec, const float* __restrict__ W,
                                  const float* __restrict__ bo, float* __restrict__ outp)
{
    int tid = threadIdx.x;  // 256
    float a0 = 0.f, a1 = 0.f;
#pragma unroll
    for (int hh = 0; hh < 4; hh++) {
        int idx = tid * 4 + hh;
        float x = tanhf(bvec[idx]);
        a0 = fmaf(x, W[idx * 2],     a0);
        a1 = fmaf(x, W[idx * 2 + 1], a1);
    }
#pragma unroll
    for (int o = 16; o > 0; o >>= 1) {
        a0 += __shfl_down_sync(0xffffffffu, a0, o);
        a1 += __shfl_down_sync(0xffffffffu, a1, o);
    }
    __shared__ float s0[8], s1[8];
    int wid = tid >> 5, lane = tid & 31;
    if (lane == 0) { s0[wid] = a0; s1[wid] = a1; }
    __syncthreads();
    if (tid == 0) {
        float t0 = 0.f, t1 = 0.f;
        for (int q = 0; q < 8; q++) { t0 += s0[q]; t1 += s1[q]; }
        outp[0] = t0 + bo[0];
        outp[1] = t1 + bo[1];
    }
}

__global__ void prep_kernel(const float* __restrict__ b_naf, const float* __restrict__ b_cd,
                            const float* __restrict__ b_nd,  const float* __restrict__ b_ed,
                            const float* __restrict__ W_no,  const float* __restrict__ b_no,
                            const float* __restrict__ W_eo,  const float* __restrict__ b_eo)
{
    int blk = blockIdx.x;
    if (blk < 12) {
        int t = blk * 256 + threadIdx.x;
        if (t < 2048) g_bcat2[t] = (t < 1024) ? b_naf[t] : b_cd[t - 1024];
        if (t < 3072) g_bcat3[t] = (t < 1024) ? b_nd[t] : ((t < 2048) ? b_ed[t - 1024] : 0.0f);
    } else if (blk == 12) {
        head_const_region(b_nd, W_no, b_no, g_zlog);
    } else {
        head_const_region(b_ed, W_eo, b_eo, g_elog);
    }
}

// ---------------- segment means + counts ----------------
__global__ void seg_kernel(const float* __restrict__ seq, const int* __restrict__ off)
{
    int b = blockIdx.x, m = blockIdx.y;
    __shared__ int soff[25];
    int tid = threadIdx.x;
    if (tid < 25) soff[tid] = off[b * 25 + tid];
    __syncthreads();
    int c = 0;
#pragma unroll
    for (int q = 0; q < 25; q++) c += (soff[q] > 0);
    if (m == 0 && tid == 0) g_count[b] = c;

    float* dst = g_node + ((size_t)b * 26 + m) * 1024 + tid * 4;
    if (m >= c) { float4 z = {0.f, 0.f, 0.f, 0.f}; *(float4*)dst = z; return; }
    int e  = soff[m];
    int s0 = (m ? soff[m - 1] : 0) + 1;
    int len = e - s0 + 1;
    const float* p = seq + ((size_t)b * 512 + s0) * 1024 + tid * 4;
    float4 acc = {0.f, 0.f, 0.f, 0.f};
#pragma unroll 4
    for (int s = 0; s < len; s++) {
        float4 v = *(const float4*)(p + (size_t)s * 1024);
        acc.x += v.x; acc.y += v.y; acc.z += v.z; acc.w += v.w;
    }
    float inv = 1.0f / (float)len;
    float4 r = {acc.x * inv, acc.y * inv, acc.z * inv, acc.w * inv};
    *(float4*)dst = r;
}

// ---------------- prefix + rowmap ----------------
__global__ void prefix_kernel()
{
    __shared__ int sc[64], sp[64];
    int tid = threadIdx.x;
    if (tid < 64) sc[tid] = g_count[tid];
    __syncthreads();
    if (tid == 0) {
        int p = 0;
        for (int b = 0; b < 64; b++) { sp[b] = p; g_pref[b] = p; p += sc[b] + 1; }
        g_R = p;
    }
    __syncthreads();
    for (int r = tid; r < 1664; r += 256) {
        int b = r / 26, m = r - b * 26;
        if (m <= sc[b]) g_rowmap[sp[b] + m] = r;
    }
}

// ---------------- node_full[b,count[b],:] += naf ----------------
__global__ void scatter_naf_kernel()
{
    int b = blockIdx.x, tid = threadIdx.x;
    int c = g_count[b];
    float* dst = g_node + ((size_t)b * 26 + c) * 1024 + tid * 4;
    const float* naf = g_C2 + (size_t)b * 2048 + tid * 4;
    float4 d = *(float4*)dst;
    float4 n = *(const float4*)naf;
    d.x += n.x; d.y += n.y; d.z += n.z; d.w += n.w;
    *(float4*)dst = d;
}

// ---------------- A packs (fragment order, hi/lo) ----------------
__global__ void packAnode_kernel()
{
    int mb = blockIdx.x, s = blockIdx.y;
    int R = g_R;
    if (mb * 128 >= R) return;
    __half* tile = g_ApackN + ((size_t)(mb * 32 + s)) * 8192;
    for (int c = threadIdx.x; c < 512; c += 256) {
        int kk16 = c >> 8, mt16 = (c >> 5) & 7, lane = c & 31;
        int gq = lane >> 2, tg = lane & 3;
        int kb = s * 32 + kk16 * 16 + 2 * tg;
        int r0 = mb * 128 + mt16 * 16 + gq, r1 = r0 + 8;
        float x0[4] = {0,0,0,0}, x1[4] = {0,0,0,0};
        if (r0 < R) { const float* p = g_node + (size_t)g_rowmap[r0] * 1024 + kb;
                      x0[0]=p[0]; x0[1]=p[1]; x0[2]=p[8]; x0[3]=p[9]; }
        if (r1 < R) { const float* p = g_node + (size_t)g_rowmap[r1] * 1024 + kb;
                      x1[0]=p[0]; x1[1]=p[1]; x1[2]=p[8]; x1[3]=p[9]; }
        uint4 hi, lo;
        hl2(x0[0], x0[1], hi.x, lo.x);
        hl2(x1[0], x1[1], hi.y, lo.y);
        hl2(x0[2], x0[3], hi.z, lo.z);
        hl2(x1[2], x1[3], hi.w, lo.w);
        uint32_t off = (uint32_t)(kk16 * 8 + mt16) * 512 + lane * 16;
        *(uint4*)((char*)tile + off)        = hi;
        *(uint4*)((char*)tile + 8192 + off) = lo;
    }
}

__global__ void packAcls_kernel(const float* __restrict__ seq)
{
    int s = blockIdx.x;
    __half* tile = g_ApackC + ((size_t)s) * 8192;
    for (int c = threadIdx.x; c < 512; c += 256) {
        int kk16 = c >> 8, mt16 = (c >> 5) & 7, lane = c & 31;
        int gq = lane >> 2, tg = lane & 3;
        int kb = s * 32 + kk16 * 16 + 2 * tg;
        int r0 = mt16 * 16 + gq, r1 = r0 + 8;
        float x0[4] = {0,0,0,0}, x1[4] = {0,0,0,0};
        if (r0 < 64) { const float* p = seq + (size_t)r0 * 524288 + kb;
                       x0[0]=p[0]; x0[1]=p[1]; x0[2]=p[8]; x0[3]=p[9]; }
        if (r1 < 64) { const float* p = seq + (size_t)r1 * 524288 + kb;
                       x1[0]=p[0]; x1[1]=p[1]; x1[2]=p[8]; x1[3]=p[9]; }
        uint4 hi, lo;
        hl2(x0[0], x0[1], hi.x, lo.x);
        hl2(x1[0], x1[1], hi.y, lo.y);
        hl2(x0[2], x0[3], hi.z, lo.z);
        hl2(x1[2], x1[3], hi.w, lo.w);
        uint32_t off = (uint32_t)(kk16 * 8 + mt16) * 512 + lane * 16;
        *(uint4*)((char*)tile + off)        = hi;
        *(uint4*)((char*)tile + 8192 + off) = lo;
    }
}

// ---------------- B packs (float4-staged, fragment order, hi/lo) ----------------
__device__ void packB_region(int nb, int s, const float* __restrict__ Wa,
                             const float* __restrict__ Wb, int which,
                             __half* __restrict__ Bpack)
{
    __shared__ __align__(16) float ws[32][132];
    // stage 32k x 128n with float4 loads (region uniform per 128-col tile)
    for (int e = threadIdx.x; e < 32 * 32; e += 256) {
        int k = e >> 5, n4 = (e & 31) << 2;
        int kg = s * 32 + k, ng = nb * 128 + n4;
        float4 v;
        if (which == 0) {
            v = (ng < 1024) ? ld4(Wa + (size_t)kg * 1024 + ng)
                            : ld4(Wb + (size_t)kg * 1024 + (ng - 1024));
        } else {
            if (ng < 1024) {
                v = ld4(Wa + (size_t)kg * 1024 + ng);
            } else if (ng < 2048) {
                int cc = ng - 1024;
                float4 a = ld4(Wb + (size_t)kg * 1024 + cc);
                float4 b = ld4(Wb + (size_t)(2048 + kg) * 1024 + cc);
                v = make_float4(a.x + b.x, a.y + b.y, a.z + b.z, a.w + b.w);
            } else {
                int cc = ng - 2048;
                float4 a = ld4(Wb + (size_t)(1024 + kg) * 1024 + cc);
                float4 b = ld4(Wb + (size_t)(2048 + kg) * 1024 + cc);
                v = make_float4(a.x - b.x, a.y - b.y, a.z - b.z, a.w - b.w);
            }
        }
        *(float4*)&ws[k][n4] = v;
    }
    __syncthreads();
    __half* tile = Bpack + ((size_t)(nb * 32 + s)) * 8192;
    for (int c = threadIdx.x; c < 512; c += 256) {
        int kk16 = c >> 8, nt16b = (c >> 5) & 7, lane = c & 31;
        int gq = lane >> 2, tg = lane & 3;
        int kl = kk16 * 16 + 2 * tg;
        int ne = nt16b * 16 + gq, no = ne + 8;
        uint4 hi, lo;
        hl2(ws[kl][ne],     ws[kl + 1][ne], hi.x, lo.x);
        hl2(ws[kl + 8][ne], ws[kl + 9][ne], hi.y, lo.y);
        hl2(ws[kl][no],     ws[kl + 1][no], hi.z, lo.z);
        hl2(ws[kl + 8][no], ws[kl + 9][no], hi.w, lo.w);
        uint32_t off = (uint32_t)(kk16 * 8 + nt16b) * 512 + lane * 16;
        *(uint4*)((char*)tile + off)        = hi;
        *(uint4*)((char*)tile + 8192 + off) = lo;
    }
}

__global__ void packB3_kernel(const float* __restrict__ W_nd, const float* __restrict__ W_ed)
{ packB_region(blockIdx.x, blockIdx.y, W_nd, W_ed, 1, g_BpackN); }
__global__ void packB2_kernel(const float* __restrict__ W_naf, const float* __restrict__ W_cd)
{ packB_region(blockIdx.x, blockIdx.y, W_naf, W_cd, 0, g_BpackC); }

// ---------------- fp16 3-term GEMM, block 64x128, BK=32, 256 thr ----------------
// stage: A 8KB (hi 4K|lo 4K) ++ B 16KB (hi 8K|lo 8K) = 24KB, double buffered 48KB
#define STAGE 24576
__global__ __launch_bounds__(256) void gemm3_kernel(
    const __half* __restrict__ Apack, const __half* __restrict__ Bpack,
    const float* __restrict__ bias, float* __restrict__ C, int ldc,
    const int* __restrict__ Mptr, int tanh_lo, int tanh_hi)
{
    int R = *Mptr;
    int mb = blockIdx.x, nb = blockIdx.y;
    if (mb * 64 >= R) return;
    int mb128 = mb >> 1, mhalf4 = (mb & 1) * 4;
    extern __shared__ char sm[];
    uint32_t sb = smem_u32(sm);
    int tid = threadIdx.x, lane = tid & 31, w = tid >> 5;
    int gq = lane >> 2, tg = lane & 3;
    int wmt = (w & 1) * 2;            // warp mt base (2 x 16 rows)
    int wnb = (w >> 1) * 2;           // warp nt16b base

    const char* Ab = (const char*)Apack + (size_t)(mb128 * 32) * 16384;
    const char* Bb = (const char*)Bpack + (size_t)(nb * 32) * 16384;

    // A copy source offset (per thread, constant over slabs)
    uint32_t aoff = (uint32_t)((tid >> 7) * 8 + mhalf4 + ((tid >> 5) & 3)) * 512 + (tid & 31) * 16;

    float    acc [2][4][4];
    uint32_t accH[2][4][2];
#pragma unroll
    for (int mt = 0; mt < 2; mt++)
#pragma unroll
        for (int nt = 0; nt < 4; nt++) {
#pragma unroll
            for (int q = 0; q < 4; q++) acc[mt][nt][q] = 0.f;
            accH[mt][nt][0] = 0u; accH[mt][nt][1] = 0u;
        }

#define COPY_STAGE(dstb, s_) do { \
    const char* As_ = Ab + (size_t)(s_) * 16384; \
    const char* Bs_ = Bb + (size_t)(s_) * 16384; \
    CP16((dstb) + tid * 16,          As_ + aoff); \
    CP16((dstb) + 4096 + tid * 16,   As_ + 8192 + aoff); \
    CP16((dstb) + 8192  + tid * 16,  Bs_ + tid * 16); \
    CP16((dstb) + 12288 + tid * 16,  Bs_ + 4096 + tid * 16); \
    CP16((dstb) + 16384 + tid * 16,  Bs_ + 8192 + tid * 16); \
    CP16((dstb) + 20480 + tid * 16,  Bs_ + 12288 + tid * 16); \
    CP_COMMIT(); \
} while (0)

    COPY_STAGE(sb, 0);

    for (int s = 0; s < 32; s++) {
        if (s < 31) {
            COPY_STAGE(sb + ((s + 1) & 1) * STAGE, s + 1);
            CP_WAIT1();
        } else {
            CP_WAIT0();
        }
        __syncthreads();
        const char* st = sm + (s & 1) * STAGE;
#pragma unroll
        for (int kk = 0; kk < 2; kk++) {
            uint4 Ah[2], Al[2];
#pragma unroll
            for (int mt = 0; mt < 2; mt++) {
                uint32_t ao = (uint32_t)(kk * 4 + wmt + mt) * 512 + lane * 16;
                Ah[mt] = *(const uint4*)(st + ao);
                Al[mt] = *(const uint4*)(st + 4096 + ao);
            }
#pragma unroll
            for (int ntb = 0; ntb < 2; ntb++) {
                uint32_t bo = (uint32_t)(kk * 8 + wnb + ntb) * 512 + lane * 16;
                uint4 bh = *(const uint4*)(st + 8192 + bo);
                uint4 bl = *(const uint4*)(st + 16384 + bo);
#pragma unroll
                for (int mt = 0; mt < 2; mt++) {
                    MMA16 (acc [mt][2 * ntb],     Ah[mt], bh.x, bh.y);
                    MMA16H(accH[mt][2 * ntb],     Al[mt], bh.x, bh.y);
                    MMA16H(accH[mt][2 * ntb],     Ah[mt], bl.x, bl.y);
                    MMA16 (acc [mt][2 * ntb + 1], Ah[mt], bh.z, bh.w);
                    MMA16H(accH[mt][2 * ntb + 1], Al[mt], bh.z, bh.w);
                    MMA16H(accH[mt][2 * ntb + 1], Ah[mt], bl.z, bl.w);
                }
            }
        }
        __syncthreads();
    }

    bool dt = (nb * 128 >= tanh_lo) && (nb * 128 < tanh_hi);
#pragma unroll
    for (int nt = 0; nt < 4; nt++) {
        int col = nb * 128 + (w >> 1) * 32 + nt * 8 + 2 * tg;
        float b0 = bias[col], b1 = bias[col + 1];
#pragma unroll
        for (int mt = 0; mt < 2; mt++) {
            int row = mb * 64 + (w & 1) * 32 + mt * 16 + gq;
            __half2 h01 = *(__half2*)&accH[mt][nt][0];
            __half2 h23 = *(__half2*)&accH[mt][nt][1];
            float v0 = acc[mt][nt][0] + __low2float(h01)  + b0;
            float v1 = acc[mt][nt][1] + __high2float(h01) + b1;
            float v2 = acc[mt][nt][2] + __low2float(h23)  + b0;
            float v3 = acc[mt][nt][3] + __high2float(h23) + b1;
            if (dt) { v0 = ftanh(v0); v1 = ftanh(v1); v2 = ftanh(v2); v3 = ftanh(v3); }
            if (row < R)     { float2 p = {v0, v1}; *(float2*)(C + (size_t)row * ldc + col) = p; }
            if (row + 8 < R) { float2 p = {v2, v3}; *(float2*)(C + (size_t)(row + 8) * ldc + col) = p; }
        }
    }
}

// ---------------- heads ----------------
__global__ void head_kernel(const float* __restrict__ W_co, const float* __restrict__ b_co,
                            const float* __restrict__ W_no, const float* __restrict__ b_no,
                            float* __restrict__ out)
{
    int blk = blockIdx.x, tid = threadIdx.x;   // 128 threads
    const float* x; const float* Wv; const float* bs; float* op;
    if (blk < 64) {
        x  = g_C2 + (size_t)blk * 2048 + 1024;
        Wv = W_co; bs = b_co; op = out + blk * 2;
    } else {
        int r = blk - 64;
        int b = r / 26, m = r - b * 26;
        op = out + 128 + r * 2;
        if (m > g_count[b]) {
            if (tid == 0) { op[0] = g_zlog[0]; op[1] = g_zlog[1]; }
            return;
        }
        x  = g_Cbig + (size_t)(g_pref[b] + m) * 3072;
        Wv = W_no; bs = b_no;
    }
    float xs[8], ws[16];
    {
        const float4* xv = (const float4*)(x + tid * 8);
        *(float4*)xs       = xv[0];
        *(float4*)(xs + 4) = xv[1];
        const float4* wv = (const float4*)(Wv + tid * 16);
#pragma unroll
        for (int q = 0; q < 4; q++) *(float4*)(ws + q * 4) = wv[q];
    }
    float a0 = 0.f, a1 = 0.f;
#pragma unroll
    for (int hh = 0; hh < 8; hh++) {
        a0 = fmaf(xs[hh], ws[2 * hh], a0);
        a1 = fmaf(xs[hh], ws[2 * hh + 1], a1);
    }
#pragma unroll
    for (int o = 16; o > 0; o >>= 1) {
        a0 += __shfl_down_sync(0xffffffffu, a0, o);
        a1 += __shfl_down_sync(0xffffffffu, a1, o);
    }
    __shared__ float s0[4], s1[4];
    int wid = tid >> 5, lane = tid & 31;
    if (lane == 0) { s0[wid] = a0; s1[wid] = a1; }
    __syncthreads();
    if (tid == 0) {
        op[0] = s0[0] + s0[1] + s0[2] + s0[3] + bs[0];
        op[1] = s1[0] + s1[1] + s1[2] + s1[3] + bs[1];
    }
}

// ---------------- edge logits ----------------
__global__ void edge_kernel(const float* __restrict__ W_eo, const float* __restrict__ b_eo,
                            float* __restrict__ out)
{
    int ke = blockIdx.x;
    int b  = ke / 676;
    int k  = ke - b * 676;
    int n  = g_count[b] + 1;
    int tid = threadIdx.x;   // 128
    float* op = out + 3456 + (size_t)ke * 2;

    if (k >= n * n) {                       // invalid edge -> precomputed constant
        if (tid == 0) { op[0] = g_elog[0]; op[1] = g_elog[1]; }
        return;
    }
    int i = k / n, j = k - i * n;
    int pj = g_pref[b] + j, pi = g_pref[b] + i;
    const float* U = g_Cbig + (size_t)pj * 3072 + 1024 + tid * 8;
    const float* V = g_Cbig + (size_t)pi * 3072 + 2048 + tid * 8;
    float us[8], vs[8], xs[8];
    *(float4*)us       = ((const float4*)U)[0];
    *(float4*)(us + 4) = ((const float4*)U)[1];
    *(float4*)vs       = ((const float4*)V)[0];
    *(float4*)(vs + 4) = ((const float4*)V)[1];
#pragma unroll
    for (int hh = 0; hh < 8; hh++) xs[hh] = ftanh(us[hh] + vs[hh]);

    float ws[16];
    {
        const float4* wv = (const float4*)(W_eo + tid * 16);
#pragma unroll
        for (int q = 0; q < 4; q++) *(float4*)(ws + q * 4) = wv[q];
    }
    float a0 = 0.f, a1 = 0.f;
#pragma unroll
    for (int hh = 0; hh < 8; hh++) {
        a0 = fmaf(xs[hh], ws[2 * hh], a0);
        a1 = fmaf(xs[hh], ws[2 * hh + 1], a1);
    }
#pragma unroll
    for (int o = 16; o > 0; o >>= 1) {
        a0 += __shfl_down_sync(0xffffffffu, a0, o);
        a1 += __shfl_down_sync(0xffffffffu, a1, o);
    }
    __shared__ float s0[4], s1[4];
    int wid = tid >> 5, lane = tid & 31;
    if (lane == 0) { s0[wid] = a0; s1[wid] = a1; }
    __syncthreads();
    if (tid == 0) {
        op[0] = s0[0] + s0[1] + s0[2] + s0[3] + b_eo[0];
        op[1] = s1[0] + s1[1] + s1[2] + s1[3] + b_eo[1];
    }
}

// ---------------- launch ----------------
extern "C" void kernel_launch(void* const* d_in, const int* in_sizes, int n_in,
                              void* d_out, int out_size)
{
    const float* seq   = (const float*)d_in[0];
    const int*   off   = (const int*)d_in[1];
    const float* W_naf = (const float*)d_in[4];
    const float* b_naf = (const float*)d_in[5];
    const float* W_cd  = (const float*)d_in[6];
    const float* b_cd  = (const float*)d_in[7];
    const float* W_co  = (const float*)d_in[8];
    const float* b_co  = (const float*)d_in[9];
    const float* W_nd  = (const float*)d_in[10];
    const float* b_nd  = (const float*)d_in[11];
    const float* W_no  = (const float*)d_in[12];
    const float* b_no  = (const float*)d_in[13];
    const float* W_ed  = (const float*)d_in[14];
    const float* b_ed  = (const float*)d_in[15];
    const float* W_eo  = (const float*)d_in[16];
    const float* b_eo  = (const float*)d_in[17];
    float* out = (float*)d_out;

    float *pbcat2, *pbcat3, *pC2, *pCbig;
    __half *pApN, *pApC, *pBpN, *pBpC;
    int *pR, *pM1;
    cudaGetSymbolAddress((void**)&pbcat2, g_bcat2);
    cudaGetSymbolAddress((void**)&pbcat3, g_bcat3);
    cudaGetSymbolAddress((void**)&pC2,    g_C2);
    cudaGetSymbolAddress((void**)&pCbig,  g_Cbig);
    cudaGetSymbolAddress((void**)&pApN,   g_ApackN);
    cudaGetSymbolAddress((void**)&pApC,   g_ApackC);
    cudaGetSymbolAddress((void**)&pBpN,   g_BpackN);
    cudaGetSymbolAddress((void**)&pBpC,   g_BpackC);
    cudaGetSymbolAddress((void**)&pR,     g_R);
    cudaGetSymbolAddress((void**)&pM1,    g_M1);

    cudaFuncSetAttribute(gemm3_kernel, cudaFuncAttributeMaxDynamicSharedMemorySize, 2 * STAGE);

    // weight-only prep
    prep_kernel<<<14, 256>>>(b_naf, b_cd, b_nd, b_ed, W_no, b_no, W_eo, b_eo);
    packB3_kernel<<<dim3(24, 32), 256>>>(W_nd, W_ed);
    packB2_kernel<<<dim3(16, 32), 256>>>(W_naf, W_cd);
    // data path
    seg_kernel<<<dim3(64, 26), 256>>>(seq, off);
    prefix_kernel<<<1, 256>>>();
    packAcls_kernel<<<32, 256>>>(seq);
    // G1: cls @ [W_naf | W_cd] -> g_C2 (tanh cols [1024,2048))
    gemm3_kernel<<<dim3(1, 16), 256, 2 * STAGE>>>(pApC, pBpC, pbcat2, pC2, 2048, pM1, 1024, 2048);
    scatter_naf_kernel<<<64, 256>>>();
    packAnode_kernel<<<dim3(13, 32), 256>>>();
    // G2: nodeC @ [W_nd | W1+W3 | W2-W3] -> g_Cbig (tanh cols [0,1024))
    gemm3_kernel<<<dim3(26, 24), 256, 2 * STAGE>>>(pApN, pBpN, pbcat3, pCbig, 3072, pR, 0, 1024);
    // heads
    head_kernel<<<64 + 1664, 128>>>(W_co, b_co, W_no, b_no, out);
    edge_kernel<<<64 * 676, 128>>>(W_eo, b_eo, out);
}

// round 8
// speedup vs baseline: 3.0559x; 1.3383x over previous
#include <cuda_runtime.h>
#include <cuda_fp16.h>
#include <math.h>
#include <stdint.h>

// Shapes (fixed): B=64, S=512, H=1024, M=26, E=676
// Output: logits(64,2) ++ node_logits(64,26,2) ++ edge_logits(64,676,2) = 89984 f32
//
// GEMMs via legacy mma.m16n8k16.f16, 3-term hi/lo split; main term f32-acc,
// correction terms (Al*Bh, Ah*Bl) share an f16 accumulator.
//  G1: cls(64x1024)   @ [W_naf|W_cd](1024x2048)          -> g_C2
//  G2: nodeC(Rx1024)  @ [W_nd|W1+W3|W2-W3](1024x3072)    -> g_Cbig (compact rows)
// Segment means: balanced 32-row streaming chunks + f32 RED, normalization
// folded into the A-pack quantization.

// ---------------- scratch ----------------
__device__ float g_bcat2[2048];
__device__ float g_bcat3[3072];
__device__ float g_node[64 * 26 * 1024];
__device__ float g_C2[64 * 2048];
__device__ float g_Cbig[1664 * 3072];    // compact rows used: [T_nd | U | V]
__device__ int   g_count[64];
__device__ int   g_pref[64];
__device__ int   g_rowmap[1664];
__device__ float g_invlen[1664];
__device__ int   g_R;
__device__ int   g_M1 = 64;
__device__ float g_zlog[2];
__device__ float g_elog[2];

// pre-fragmented fp16 hi/lo packs (slab = 128rows x 32k: hi 8KB + lo 8KB)
__device__ __align__(16) __half g_ApackN[13 * 32 * 8192];
__device__ __align__(16) __half g_ApackC[32 * 8192];
__device__ __align__(16) __half g_BpackN[24 * 32 * 8192];
__device__ __align__(16) __half g_BpackC[16 * 32 * 8192];

// ---------------- helpers ----------------
__device__ __forceinline__ uint32_t smem_u32(const void* p) {
    uint32_t a;
    asm("{ .reg .u64 t; cvta.to.shared.u64 t, %1; cvt.u32.u64 %0, t; }" : "=r"(a) : "l"(p));
    return a;
}
#define CP16(dst, src) asm volatile("cp.async.cg.shared.global [%0], [%1], 16;" :: "r"(dst), "l"(src) : "memory")
#define CP_COMMIT()    asm volatile("cp.async.commit_group;" ::: "memory")
#define CP_WAIT1()     asm volatile("cp.async.wait_group 1;" ::: "memory")
#define CP_WAIT0()     asm volatile("cp.async.wait_group 0;" ::: "memory")

// f32-accumulator HMMA
#define MMA16(d, a, bb0, bb1) \
    asm volatile("mma.sync.aligned.m16n8k16.row.col.f32.f16.f16.f32 " \
                 "{%0,%1,%2,%3}, {%4,%5,%6,%7}, {%8,%9}, {%0,%1,%2,%3};" \
                 : "+f"((d)[0]), "+f"((d)[1]), "+f"((d)[2]), "+f"((d)[3]) \
                 : "r"((a).x), "r"((a).y), "r"((a).z), "r"((a).w), "r"(bb0), "r"(bb1))
// f16-accumulator HMMA (corrections)
#define MMA16H(d, a, bb0, bb1) \
    asm volatile("mma.sync.aligned.m16n8k16.row.col.f16.f16.f16.f16 " \
                 "{%0,%1}, {%2,%3,%4,%5}, {%6,%7}, {%0,%1};" \
                 : "+r"((d)[0]), "+r"((d)[1]) \
                 : "r"((a).x), "r"((a).y), "r"((a).z), "r"((a).w), "r"(bb0), "r"(bb1))

// hi/lo fp16 split of a float pair -> packed half2 regs
__device__ __forceinline__ void hl2(float a, float b, uint32_t& h, uint32_t& l) {
    __half ha = __float2half_rn(a), hb = __float2half_rn(b);
    __half la = __float2half_rn(a - __half2float(ha));
    __half lb = __float2half_rn(b - __half2float(hb));
    __half2 H = __halves2half2(ha, hb), L = __halves2half2(la, lb);
    h = *(uint32_t*)&H; l = *(uint32_t*)&L;
}

// fast tanh: 1 - 2/(exp(2x)+1) via ex2.approx + rcp.approx (~1e-6 abs err)
__device__ __forceinline__ float ftanh(float x) {
    float e;
    asm("ex2.approx.f32 %0, %1;" : "=f"(e) : "f"(x * 2.8853900817779268f));
    float r;
    asm("rcp.approx.f32 %0, %1;" : "=f"(r) : "f"(e + 1.0f));
    return fmaf(-2.0f, r, 1.0f);
}

__device__ __forceinline__ float4 ld4(const float* p) { return *(const float4*)p; }

// ---------------- zero node buffer ----------------
__global__ void zero_node_kernel()
{
    float4 z = {0.f, 0.f, 0.f, 0.f};
    *(float4*)(g_node + (size_t)blockIdx.x * 1024 + threadIdx.x * 4) = z;
}

// ---------------- prefix: counts, compact-row map, inverse lengths ----------------
__global__ void prefix_kernel(const int* __restrict__ off)
{
    __shared__ int sc[64], sp[64];
    int tid = threadIdx.x;
    if (tid < 64) {
        int c = 0;
        for (int q = 0; q < 25; q++) c += (off[tid * 25 + q] > 0);
        sc[tid] = c;
        g_count[tid] = c;
    }
    __syncthreads();
    if (tid == 0) {
        int p = 0;
        for (int b = 0; b < 64; b++) { sp[b] = p; g_pref[b] = p; p += sc[b] + 1; }
        g_R = p;
    }
    __syncthreads();
    for (int r = tid; r < 1664; r += 256) {
        int b = r / 26, m = r - b * 26;
        if (m <= sc[b]) g_rowmap[sp[b] + m] = r;
        float il = 1.0f;
        if (m < sc[b]) {
            int e = off[b * 25 + m];
            int prev = m ? off[b * 25 + m - 1] : 0;
            il = 1.0f / (float)(e - prev);
        }
        g_invlen[r] = il;
    }
}

// ---------------- prep: biases + zlog + elog (one launch) ----------------
__device__ void head_const_region(const float* __restrict__ bvec, const float* __restrict__ W,
                                  const float* __restrict__ bo, float* __restrict__ outp)
{
    int tid = threadIdx.x;  // 256
    float a0 = 0.f, a1 = 0.f;
#pragma unroll
    for (int hh = 0; hh < 4; hh++) {
        int idx = tid * 4 + hh;
        float x = tanhf(bvec[idx]);
        a0 = fmaf(x, W[idx * 2],     a0);
        a1 = fmaf(x, W[idx * 2 + 1], a1);
    }
#pragma unroll
    for (int o = 16; o > 0; o >>= 1) {
        a0 += __shfl_down_sync(0xffffffffu, a0, o);
        a1 += __shfl_down_sync(0xffffffffu, a1, o);
    }
    __shared__ float s0[8], s1[8];
    int wid = tid >> 5, lane = tid & 31;
    if (lane == 0) { s0[wid] = a0; s1[wid] = a1; }
    __syncthreads();
    if (tid == 0) {
        float t0 = 0.f, t1 = 0.f;
        for (int q = 0; q < 8; q++) { t0 += s0[q]; t1 += s1[q]; }
        outp[0] = t0 + bo[0];
        outp[1] = t1 + bo[1];
    }
}

__global__ void prep_kernel(const float* __restrict__ b_naf, const float* __restrict__ b_cd,
                            const float* __restrict__ b_nd,  const float* __restrict__ b_ed,
                            const float* __restrict__ W_no,  const float* __restrict__ b_no,
                            const float* __restrict__ W_eo,  const float* __restrict__ b_eo)
{
    int blk = blockIdx.x;
    if (blk < 12) {
        int t = blk * 256 + threadIdx.x;
        if (t < 2048) g_bcat2[t] = (t < 1024) ? b_naf[t] : b_cd[t - 1024];
        if (t < 3072) g_bcat3[t] = (t < 1024) ? b_nd[t] : ((t < 2048) ? b_ed[t - 1024] : 0.0f);
    } else if (blk == 12) {
        head_const_region(b_nd, W_no, b_no, g_zlog);
    } else {
        head_const_region(b_ed, W_eo, b_eo, g_elog);
    }
}

// ---------------- segment accumulation: balanced 32-row chunks ----------------
// grid (64, 16): batch b, s-chunk q covering rows [32q, 32q+32). Block reads a
// contiguous 128KB slab; per-segment partials flushed with f32 RED into g_node.
__global__ __launch_bounds__(256) void seg_accum_kernel(const float* __restrict__ seq,
                                                        const int* __restrict__ off)
{
    int b = blockIdx.x, q = blockIdx.y;
    __shared__ int soff[25];
    __shared__ int segid[32];
    int tid = threadIdx.x;
    if (tid < 25) soff[tid] = off[b * 25 + tid];
    __syncthreads();
    int c = 0;
#pragma unroll
    for (int m = 0; m < 25; m++) c += (soff[m] > 0);
    if (tid < 32) {
        int s = q * 32 + tid;
        int id = -1;
        if (s >= 1 && s <= soff[c - 1]) {
#pragma unroll
            for (int m = 0; m < 25; m++) {
                if (s <= soff[m]) { id = m; break; }
            }
        }
        segid[tid] = id;
    }
    __syncthreads();

    const float* base = seq + ((size_t)b * 512 + q * 32) * 1024 + tid * 4;
    float4 acc = {0.f, 0.f, 0.f, 0.f};
    int cur = -1;
#pragma unroll
    for (int g = 0; g < 4; g++) {
        float4 v[8];
#pragma unroll
        for (int r = 0; r < 8; r++) {               // 8 independent prefetch loads
            int rr = g * 8 + r;
            v[r] = (segid[rr] >= 0) ? *(const float4*)(base + (size_t)rr * 1024)
                                    : make_float4(0.f, 0.f, 0.f, 0.f);
        }
#pragma unroll
        for (int r = 0; r < 8; r++) {
            int rr = g * 8 + r;
            int id = segid[rr];
            if (id != cur) {                        // block-uniform branch
                if (cur >= 0) {
                    float* d = g_node + ((size_t)(b * 26 + cur)) * 1024 + tid * 4;
                    atomicAdd(d + 0, acc.x); atomicAdd(d + 1, acc.y);
                    atomicAdd(d + 2, acc.z); atomicAdd(d + 3, acc.w);
                }
                acc = make_float4(0.f, 0.f, 0.f, 0.f);
                cur = id;
            }
            if (id >= 0) { acc.x += v[r].x; acc.y += v[r].y; acc.z += v[r].z; acc.w += v[r].w; }
        }
    }
    if (cur >= 0) {
        float* d = g_node + ((size_t)(b * 26 + cur)) * 1024 + tid * 4;
        atomicAdd(d + 0, acc.x); atomicAdd(d + 1, acc.y);
        atomicAdd(d + 2, acc.z); atomicAdd(d + 3, acc.w);
    }
}

// ---------------- node_full[b,count[b],:] += naf ----------------
__global__ void scatter_naf_kernel()
{
    int b = blockIdx.x, tid = threadIdx.x;
    int c = g_count[b];
    float* dst = g_node + ((size_t)b * 26 + c) * 1024 + tid * 4;
    const float* naf = g_C2 + (size_t)b * 2048 + tid * 4;
    float4 d = *(float4*)dst;
    float4 n = *(const float4*)naf;
    d.x += n.x; d.y += n.y; d.z += n.z; d.w += n.w;
    *(float4*)dst = d;
}

// ---------------- A packs (fragment order, hi/lo) ----------------
// node pack applies the segment-mean normalization (g_invlen) at quantize time.
__global__ void packAnode_kernel()
{
    int mb = blockIdx.x, s = blockIdx.y;
    int R = g_R;
    if (mb * 128 >= R) return;
    __half* tile = g_ApackN + ((size_t)(mb * 32 + s)) * 8192;
    for (int c = threadIdx.x; c < 512; c += 256) {
        int kk16 = c >> 8, mt16 = (c >> 5) & 7, lane = c & 31;
        int gq = lane >> 2, tg = lane & 3;
        int kb = s * 32 + kk16 * 16 + 2 * tg;
        int r0 = mb * 128 + mt16 * 16 + gq, r1 = r0 + 8;
        float x0[4] = {0, 0, 0, 0}, x1[4] = {0, 0, 0, 0};
        if (r0 < R) {
            int src = g_rowmap[r0];
            float il = g_invlen[src];
            const float* p = g_node + (size_t)src * 1024 + kb;
            x0[0] = p[0] * il; x0[1] = p[1] * il; x0[2] = p[8] * il; x0[3] = p[9] * il;
        }
        if (r1 < R) {
            int src = g_rowmap[r1];
            float il = g_invlen[src];
            const float* p = g_node + (size_t)src * 1024 + kb;
            x1[0] = p[0] * il; x1[1] = p[1] * il; x1[2] = p[8] * il; x1[3] = p[9] * il;
        }
        uint4 hi, lo;
        hl2(x0[0], x0[1], hi.x, lo.x);
        hl2(x1[0], x1[1], hi.y, lo.y);
        hl2(x0[2], x0[3], hi.z, lo.z);
        hl2(x1[2], x1[3], hi.w, lo.w);
        uint32_t off = (uint32_t)(kk16 * 8 + mt16) * 512 + lane * 16;
        *(uint4*)((char*)tile + off)        = hi;
        *(uint4*)((char*)tile + 8192 + off) = lo;
    }
}

__global__ void packAcls_kernel(const float* __restrict__ seq)
{
    int s = blockIdx.x;
    __half* tile = g_ApackC + ((size_t)s) * 8192;
    for (int c = threadIdx.x; c < 512; c += 256) {
        int kk16 = c >> 8, mt16 = (c >> 5) & 7, lane = c & 31;
        int gq = lane >> 2, tg = lane & 3;
        int kb = s * 32 + kk16 * 16 + 2 * tg;
        int r0 = mt16 * 16 + gq, r1 = r0 + 8;
        float x0[4] = {0, 0, 0, 0}, x1[4] = {0, 0, 0, 0};
        if (r0 < 64) { const float* p = seq + (size_t)r0 * 524288 + kb;
                       x0[0] = p[0]; x0[1] = p[1]; x0[2] = p[8]; x0[3] = p[9]; }
        if (r1 < 64) { const float* p = seq + (size_t)r1 * 524288 + kb;
                       x1[0] = p[0]; x1[1] = p[1]; x1[2] = p[8]; x1[3] = p[9]; }
        uint4 hi, lo;
        hl2(x0[0], x0[1], hi.x, lo.x);
        hl2(x1[0], x1[1], hi.y, lo.y);
        hl2(x0[2], x0[3], hi.z, lo.z);
        hl2(x1[2], x1[3], hi.w, lo.w);
        uint32_t off = (uint32_t)(kk16 * 8 + mt16) * 512 + lane * 16;
        *(uint4*)((char*)tile + off)        = hi;
        *(uint4*)((char*)tile + 8192 + off) = lo;
    }
}

// ---------------- B packs (float4-staged, fragment order, hi/lo) ----------------
__device__ void packB_region(int nb, int s, const float* __restrict__ Wa,
                             const float* __restrict__ Wb, int which,
                             __half* __restrict__ Bpack)
{
    __shared__ __align__(16) float ws[32][132];
    for (int e = threadIdx.x; e < 32 * 32; e += 256) {
        int k = e >> 5, n4 = (e & 31) << 2;
        int kg = s * 32 + k, ng = nb * 128 + n4;
        float4 v;
        if (which == 0) {
            v = (ng < 1024) ? ld4(Wa + (size_t)kg * 1024 + ng)
                            : ld4(Wb + (size_t)kg * 1024 + (ng - 1024));
        } else {
            if (ng < 1024) {
                v = ld4(Wa + (size_t)kg * 1024 + ng);
            } else if (ng < 2048) {
                int cc = ng - 1024;
                float4 a = ld4(Wb + (size_t)kg * 1024 + cc);
                float4 b = ld4(Wb + (size_t)(2048 + kg) * 1024 + cc);
                v = make_float4(a.x + b.x, a.y + b.y, a.z + b.z, a.w + b.w);
            } else {
                int cc = ng - 2048;
                float4 a = ld4(Wb + (size_t)(1024 + kg) * 1024 + cc);
                float4 b = ld4(Wb + (size_t)(2048 + kg) * 1024 + cc);
                v = make_float4(a.x - b.x, a.y - b.y, a.z - b.z, a.w - b.w);
            }
        }
        *(float4*)&ws[k][n4] = v;
    }
    __syncthreads();
    __half* tile = Bpack + ((size_t)(nb * 32 + s)) * 8192;
    for (int c = threadIdx.x; c < 512; c += 256) {
        int kk16 = c >> 8, nt16b = (c >> 5) & 7, lane = c & 31;
        int gq = lane >> 2, tg = lane & 3;
        int kl = kk16 * 16 + 2 * tg;
        int ne = nt16b * 16 + gq, no = ne + 8;
        uint4 hi, lo;
        hl2(ws[kl][ne],     ws[kl + 1][ne], hi.x, lo.x);
        hl2(ws[kl + 8][ne], ws[kl + 9][ne], hi.y, lo.y);
        hl2(ws[kl][no],     ws[kl + 1][no], hi.z, lo.z);
        hl2(ws[kl + 8][no], ws[kl + 9][no], hi.w, lo.w);
        uint32_t off = (uint32_t)(kk16 * 8 + nt16b) * 512 + lane * 16;
        *(uint4*)((char*)tile + off)        = hi;
        *(uint4*)((char*)tile + 8192 + off) = lo;
    }
}

__global__ void packB3_kernel(const float* __restrict__ W_nd, const float* __restrict__ W_ed)
{ packB_region(blockIdx.x, blockIdx.y, W_nd, W_ed, 1, g_BpackN); }
__global__ void packB2_kernel(const float* __restrict__ W_naf, const float* __restrict__ W_cd)
{ packB_region(blockIdx.x, blockIdx.y, W_naf, W_cd, 0, g_BpackC); }

// ---------------- fp16 3-term GEMM, block 64x128, BK=32, 256 thr ----------------
// stage: A 8KB (hi 4K|lo 4K) ++ B 16KB (hi 8K|lo 8K) = 24KB, double buffered 48KB
#define STAGE 24576
__global__ __launch_bounds__(256) void gemm3_kernel(
    const __half* __restrict__ Apack, const __half* __restrict__ Bpack,
    const float* __restrict__ bias, float* __restrict__ C, int ldc,
    const int* __restrict__ Mptr, int tanh_lo, int tanh_hi)
{
    int R = *Mptr;
    int mb = blockIdx.x, nb = blockIdx.y;
    if (mb * 64 >= R) return;
    int mb128 = mb >> 1, mhalf4 = (mb & 1) * 4;
    extern __shared__ char sm[];
    uint32_t sb = smem_u32(sm);
    int tid = threadIdx.x, lane = tid & 31, w = tid >> 5;
    int gq = lane >> 2, tg = lane & 3;
    int wmt = (w & 1) * 2;
    int wnb = (w >> 1) * 2;

    const char* Ab = (const char*)Apack + (size_t)(mb128 * 32) * 16384;
    const char* Bb = (const char*)Bpack + (size_t)(nb * 32) * 16384;

    uint32_t aoff = (uint32_t)((tid >> 7) * 8 + mhalf4 + ((tid >> 5) & 3)) * 512 + (tid & 31) * 16;

    float    acc [2][4][4];
    uint32_t accH[2][4][2];
#pragma unroll
    for (int mt = 0; mt < 2; mt++)
#pragma unroll
        for (int nt = 0; nt < 4; nt++) {
#pragma unroll
            for (int q = 0; q < 4; q++) acc[mt][nt][q] = 0.f;
            accH[mt][nt][0] = 0u; accH[mt][nt][1] = 0u;
        }

#define COPY_STAGE(dstb, s_) do { \
    const char* As_ = Ab + (size_t)(s_) * 16384; \
    const char* Bs_ = Bb + (size_t)(s_) * 16384; \
    CP16((dstb) + tid * 16,          As_ + aoff); \
    CP16((dstb) + 4096 + tid * 16,   As_ + 8192 + aoff); \
    CP16((dstb) + 8192  + tid * 16,  Bs_ + tid * 16); \
    CP16((dstb) + 12288 + tid * 16,  Bs_ + 4096 + tid * 16); \
    CP16((dstb) + 16384 + tid * 16,  Bs_ + 8192 + tid * 16); \
    CP16((dstb) + 20480 + tid * 16,  Bs_ + 12288 + tid * 16); \
    CP_COMMIT(); \
} while (0)

    COPY_STAGE(sb, 0);

    for (int s = 0; s < 32; s++) {
        if (s < 31) {
            COPY_STAGE(sb + ((s + 1) & 1) * STAGE, s + 1);
            CP_WAIT1();
        } else {
            CP_WAIT0();
        }
        __syncthreads();
        const char* st = sm + (s & 1) * STAGE;
#pragma unroll
        for (int kk = 0; kk < 2; kk++) {
            uint4 Ah[2], Al[2];
#pragma unroll
            for (int mt = 0; mt < 2; mt++) {
                uint32_t ao = (uint32_t)(kk * 4 + wmt + mt) * 512 + lane * 16;
                Ah[mt] = *(const uint4*)(st + ao);
                Al[mt] = *(const uint4*)(st + 4096 + ao);
            }
#pragma unroll
            for (int ntb = 0; ntb < 2; ntb++) {
                uint32_t bo = (uint32_t)(kk * 8 + wnb + ntb) * 512 + lane * 16;
                uint4 bh = *(const uint4*)(st + 8192 + bo);
                uint4 bl = *(const uint4*)(st + 16384 + bo);
#pragma unroll
                for (int mt = 0; mt < 2; mt++) {
                    MMA16 (acc [mt][2 * ntb],     Ah[mt], bh.x, bh.y);
                    MMA16H(accH[mt][2 * ntb],     Al[mt], bh.x, bh.y);
                    MMA16H(accH[mt][2 * ntb],     Ah[mt], bl.x, bl.y);
                    MMA16 (acc [mt][2 * ntb + 1], Ah[mt], bh.z, bh.w);
                    MMA16H(accH[mt][2 * ntb + 1], Al[mt], bh.z, bh.w);
                    MMA16H(accH[mt][2 * ntb + 1], Ah[mt], bl.z, bl.w);
                }
            }
        }
        __syncthreads();
    }

    bool dt = (nb * 128 >= tanh_lo) && (nb * 128 < tanh_hi);
#pragma unroll
    for (int nt = 0; nt < 4; nt++) {
        int col = nb * 128 + (w >> 1) * 32 + nt * 8 + 2 * tg;
        float b0 = bias[col], b1 = bias[col + 1];
#pragma unroll
        for (int mt = 0; mt < 2; mt++) {
            int row = mb * 64 + (w & 1) * 32 + mt * 16 + gq;
            __half2 h01 = *(__half2*)&accH[mt][nt][0];
            __half2 h23 = *(__half2*)&accH[mt][nt][1];
            float v0 = acc[mt][nt][0] + __low2float(h01)  + b0;
            float v1 = acc[mt][nt][1] + __high2float(h01) + b1;
            float v2 = acc[mt][nt][2] + __low2float(h23)  + b0;
            float v3 = acc[mt][nt][3] + __high2float(h23) + b1;
            if (dt) { v0 = ftanh(v0); v1 = ftanh(v1); v2 = ftanh(v2); v3 = ftanh(v3); }
            if (row < R)     { float2 p = {v0, v1}; *(float2*)(C + (size_t)row * ldc + col) = p; }
            if (row + 8 < R) { float2 p = {v2, v3}; *(float2*)(C + (size_t)(row + 8) * ldc + col) = p; }
        }
    }
}

// ---------------- heads ----------------
__global__ void head_kernel(const float* __restrict__ W_co, const float* __restrict__ b_co,
                            const float* __restrict__ W_no, const float* __restrict__ b_no,
                            float* __restrict__ out)
{
    int blk = blockIdx.x, tid = threadIdx.x;   // 128 threads
    const float* x; const float* Wv; const float* bs; float* op;
    if (blk < 64) {
        x  = g_C2 + (size_t)blk * 2048 + 1024;
        Wv = W_co; bs = b_co; op = out + blk * 2;
    } else {
        int r = blk - 64;
        int b = r / 26, m = r - b * 26;
        op = out + 128 + r * 2;
        if (m > g_count[b]) {
            if (tid == 0) { op[0] = g_zlog[0]; op[1] = g_zlog[1]; }
            return;
        }
        x  = g_Cbig + (size_t)(g_pref[b] + m) * 3072;
        Wv = W_no; bs = b_no;
    }
    float xs[8], ws[16];
    {
        const float4* xv = (const float4*)(x + tid * 8);
        *(float4*)xs       = xv[0];
        *(float4*)(xs + 4) = xv[1];
        const float4* wv = (const float4*)(Wv + tid * 16);
#pragma unroll
        for (int q = 0; q < 4; q++) *(float4*)(ws + q * 4) = wv[q];
    }
    float a0 = 0.f, a1 = 0.f;
#pragma unroll
    for (int hh = 0; hh < 8; hh++) {
        a0 = fmaf(xs[hh], ws[2 * hh], a0);
        a1 = fmaf(xs[hh], ws[2 * hh + 1], a1);
    }
#pragma unroll
    for (int o = 16; o > 0; o >>= 1) {
        a0 += __shfl_down_sync(0xffffffffu, a0, o);
        a1 += __shfl_down_sync(0xffffffffu, a1, o);
    }
    __shared__ float s0[4], s1[4];
    int wid = tid >> 5, lane = tid & 31;
    if (lane == 0) { s0[wid] = a0; s1[wid] = a1; }
    __syncthreads();
    if (tid == 0) {
        op[0] = s0[0] + s0[1] + s0[2] + s0[3] + bs[0];
        op[1] = s1[0] + s1[1] + s1[2] + s1[3] + bs[1];
    }
}

// ---------------- edge logits ----------------
__global__ void edge_kernel(const float* __restrict__ W_eo, const float* __restrict__ b_eo,
                            float* __restrict__ out)
{
    int ke = blockIdx.x;
    int b  = ke / 676;
    int k  = ke - b * 676;
    int n  = g_count[b] + 1;
    int tid = threadIdx.x;   // 128
    float* op = out + 3456 + (size_t)ke * 2;

    if (k >= n * n) {                       // invalid edge -> precomputed constant
        if (tid == 0) { op[0] = g_elog[0]; op[1] = g_elog[1]; }
        return;
    }
    int i = k / n, j = k - i * n;
    int pj = g_pref[b] + j, pi = g_pref[b] + i;
    const float* U = g_Cbig + (size_t)pj * 3072 + 1024 + tid * 8;
    const float* V = g_Cbig + (size_t)pi * 3072 + 2048 + tid * 8;
    float us[8], vs[8], xs[8];
    *(float4*)us       = ((const float4*)U)[0];
    *(float4*)(us + 4) = ((const float4*)U)[1];
    *(float4*)vs       = ((const float4*)V)[0];
    *(float4*)(vs + 4) = ((const float4*)V)[1];
#pragma unroll
    for (int hh = 0; hh < 8; hh++) xs[hh] = ftanh(us[hh] + vs[hh]);

    float ws[16];
    {
        const float4* wv = (const float4*)(W_eo + tid * 16);
#pragma unroll
        for (int q = 0; q < 4; q++) *(float4*)(ws + q * 4) = wv[q];
    }
    float a0 = 0.f, a1 = 0.f;
#pragma unroll
    for (int hh = 0; hh < 8; hh++) {
        a0 = fmaf(xs[hh], ws[2 * hh], a0);
        a1 = fmaf(xs[hh], ws[2 * hh + 1], a1);
    }
#pragma unroll
    for (int o = 16; o > 0; o >>= 1) {
        a0 += __shfl_down_sync(0xffffffffu, a0, o);
        a1 += __shfl_down_sync(0xffffffffu, a1, o);
    }
    __shared__ float s0[4], s1[4];
    int wid = tid >> 5, lane = tid & 31;
    if (lane == 0) { s0[wid] = a0; s1[wid] = a1; }
    __syncthreads();
    if (tid == 0) {
        op[0] = s0[0] + s0[1] + s0[2] + s0[3] + b_eo[0];
        op[1] = s1[0] + s1[1] + s1[2] + s1[3] + b_eo[1];
    }
}

// ---------------- launch ----------------
extern "C" void kernel_launch(void* const* d_in, const int* in_sizes, int n_in,
                              void* d_out, int out_size)
{
    const float* seq   = (const float*)d_in[0];
    const int*   off   = (const int*)d_in[1];
    const float* W_naf = (const float*)d_in[4];
    const float* b_naf = (const float*)d_in[5];
    const float* W_cd  = (const float*)d_in[6];
    const float* b_cd  = (const float*)d_in[7];
    const float* W_co  = (const float*)d_in[8];
    const float* b_co  = (const float*)d_in[9];
    const float* W_nd  = (const float*)d_in[10];
    const float* b_nd  = (const float*)d_in[11];
    const float* W_no  = (const float*)d_in[12];
    const float* b_no  = (const float*)d_in[13];
    const float* W_ed  = (const float*)d_in[14];
    const float* b_ed  = (const float*)d_in[15];
    const float* W_eo  = (const float*)d_in[16];
    const float* b_eo  = (const float*)d_in[17];
    float* out = (float*)d_out;

    float *pbcat2, *pbcat3, *pC2, *pCbig;
    __half *pApN, *pApC, *pBpN, *pBpC;
    int *pR, *pM1;
    cudaGetSymbolAddress((void**)&pbcat2, g_bcat2);
    cudaGetSymbolAddress((void**)&pbcat3, g_bcat3);
    cudaGetSymbolAddress((void**)&pC2,    g_C2);
    cudaGetSymbolAddress((void**)&pCbig,  g_Cbig);
    cudaGetSymbolAddress((void**)&pApN,   g_ApackN);
    cudaGetSymbolAddress((void**)&pApC,   g_ApackC);
    cudaGetSymbolAddress((void**)&pBpN,   g_BpackN);
    cudaGetSymbolAddress((void**)&pBpC,   g_BpackC);
    cudaGetSymbolAddress((void**)&pR,     g_R);
    cudaGetSymbolAddress((void**)&pM1,    g_M1);

    cudaFuncSetAttribute(gemm3_kernel, cudaFuncAttributeMaxDynamicSharedMemorySize, 2 * STAGE);

    // seg pipeline first (seg_accum is the 4th launch -> ncu profiles it)
    zero_node_kernel<<<1664, 256>>>();
    prefix_kernel<<<1, 256>>>(off);
    prep_kernel<<<14, 256>>>(b_naf, b_cd, b_nd, b_ed, W_no, b_no, W_eo, b_eo);
    seg_accum_kernel<<<dim3(64, 16), 256>>>(seq, off);
    // weight packs
    packB3_kernel<<<dim3(24, 32), 256>>>(W_nd, W_ed);
    packB2_kernel<<<dim3(16, 32), 256>>>(W_naf, W_cd);
    packAcls_kernel<<<32, 256>>>(seq);
    // G1: cls @ [W_naf | W_cd] -> g_C2 (tanh cols [1024,2048))
    gemm3_kernel<<<dim3(1, 16), 256, 2 * STAGE>>>(pApC, pBpC, pbcat2, pC2, 2048, pM1, 1024, 2048);
    scatter_naf_kernel<<<64, 256>>>();
    packAnode_kernel<<<dim3(13, 32), 256>>>();
    // G2: nodeC @ [W_nd | W1+W3 | W2-W3] -> g_Cbig (tanh cols [0,1024))
    gemm3_kernel<<<dim3(26, 24), 256, 2 * STAGE>>>(pApN, pBpN, pbcat3, pCbig, 3072, pR, 0, 1024);
    // heads
    head_kernel<<<64 + 1664, 128>>>(W_co, b_co, W_no, b_no, out);
    edge_kernel<<<64 * 676, 128>>>(W_eo, b_eo, out);
}

// round 9
// speedup vs baseline: 3.3706x; 1.1030x over previous
#include <cuda_runtime.h>
#include <cuda_fp16.h>
#include <math.h>
#include <stdint.h>

// Shapes (fixed): B=64, S=512, H=1024, M=26, E=676
// Output: logits(64,2) ++ node_logits(64,26,2) ++ edge_logits(64,676,2) = 89984 f32
//
// 6-launch pipeline:
//  K_front : zero g_node | prefix/rowmap/invlen | biases+const-heads | packB3 | packB2 | packAcls
//  seg_accum: balanced 32-row streaming chunks + f32 RED into g_node
//  G1 (gemm3 mode 1): cls @ [W_naf|W_cd]; naf half scattered directly into g_node
//  packAnode: compact rows -> fragment-order fp16 hi/lo (normalization folded in)
//  G2 (gemm3 mode 0): nodeC @ [W_nd|W1+W3|W2-W3] -> g_Cbig
//  K_tail  : logits | node_logits | edge_logits

// ---------------- scratch ----------------
__device__ float g_bcat2[2048];
__device__ float g_bcat3[3072];
__device__ float g_node[64 * 26 * 1024];
__device__ float g_C2[64 * 2048];        // upper 1024 cols: tanh(cls@W_cd+b_cd)
__device__ float g_Cbig[1664 * 3072];    // compact rows: [T_nd | U | V]
__device__ int   g_count[64];
__device__ int   g_pref[64];
__device__ int   g_rowmap[1664];
__device__ float g_invlen[1664];
__device__ int   g_R;
__device__ int   g_M1 = 64;
__device__ float g_zlog[2];
__device__ float g_elog[2];

// pre-fragmented fp16 hi/lo packs (slab = 128rows x 32k: hi 8KB + lo 8KB)
__device__ __align__(16) __half g_ApackN[13 * 32 * 8192];
__device__ __align__(16) __half g_ApackC[32 * 8192];
__device__ __align__(16) __half g_BpackN[24 * 32 * 8192];
__device__ __align__(16) __half g_BpackC[16 * 32 * 8192];

// ---------------- helpers ----------------
__device__ __forceinline__ uint32_t smem_u32(const void* p) {
    uint32_t a;
    asm("{ .reg .u64 t; cvta.to.shared.u64 t, %1; cvt.u32.u64 %0, t; }" : "=r"(a) : "l"(p));
    return a;
}
#define CP16(dst, src) asm volatile("cp.async.cg.shared.global [%0], [%1], 16;" :: "r"(dst), "l"(src) : "memory")
#define CP_COMMIT()    asm volatile("cp.async.commit_group;" ::: "memory")
#define CP_WAIT2()     asm volatile("cp.async.wait_group 2;" ::: "memory")
#define CP_WAIT1()     asm volatile("cp.async.wait_group 1;" ::: "memory")
#define CP_WAIT0()     asm volatile("cp.async.wait_group 0;" ::: "memory")

// f32-accumulator HMMA
#define MMA16(d, a, bb0, bb1) \
    asm volatile("mma.sync.aligned.m16n8k16.row.col.f32.f16.f16.f32 " \
                 "{%0,%1,%2,%3}, {%4,%5,%6,%7}, {%8,%9}, {%0,%1,%2,%3};" \
                 : "+f"((d)[0]), "+f"((d)[1]), "+f"((d)[2]), "+f"((d)[3]) \
                 : "r"((a).x), "r"((a).y), "r"((a).z), "r"((a).w), "r"(bb0), "r"(bb1))
// f16-accumulator HMMA (corrections)
#define MMA16H(d, a, bb0, bb1) \
    asm volatile("mma.sync.aligned.m16n8k16.row.col.f16.f16.f16.f16 " \
                 "{%0,%1}, {%2,%3,%4,%5}, {%6,%7}, {%0,%1};" \
                 : "+r"((d)[0]), "+r"((d)[1]) \
                 : "r"((a).x), "r"((a).y), "r"((a).z), "r"((a).w), "r"(bb0), "r"(bb1))

// hi/lo fp16 split of a float pair -> packed half2 regs
__device__ __forceinline__ void hl2(float a, float b, uint32_t& h, uint32_t& l) {
    __half ha = __float2half_rn(a), hb = __float2half_rn(b);
    __half la = __float2half_rn(a - __half2float(ha));
    __half lb = __float2half_rn(b - __half2float(hb));
    __half2 H = __halves2half2(ha, hb), L = __halves2half2(la, lb);
    h = *(uint32_t*)&H; l = *(uint32_t*)&L;
}

// fast tanh: 1 - 2/(exp(2x)+1) via ex2.approx + rcp.approx (~1e-6 abs err)
__device__ __forceinline__ float ftanh(float x) {
    float e;
    asm("ex2.approx.f32 %0, %1;" : "=f"(e) : "f"(x * 2.8853900817779268f));
    float r;
    asm("rcp.approx.f32 %0, %1;" : "=f"(r) : "f"(e + 1.0f));
    return fmaf(-2.0f, r, 1.0f);
}

__device__ __forceinline__ float4 ld4(const float* p) { return *(const float4*)p; }

// ---------------- K_front regions ----------------
__device__ void prefix_region(const int* __restrict__ off)
{
    __shared__ int sc[64], sp[64];
    int tid = threadIdx.x;
    if (tid < 64) {
        int c = 0;
        for (int q = 0; q < 25; q++) c += (off[tid * 25 + q] > 0);
        sc[tid] = c;
        g_count[tid] = c;
    }
    __syncthreads();
    if (tid == 0) {
        int p = 0;
        for (int b = 0; b < 64; b++) { sp[b] = p; g_pref[b] = p; p += sc[b] + 1; }
        g_R = p;
    }
    __syncthreads();
    for (int r = tid; r < 1664; r += 256) {
        int b = r / 26, m = r - b * 26;
        if (m <= sc[b]) g_rowmap[sp[b] + m] = r;
        float il = 1.0f;
        if (m < sc[b]) {
            int e = off[b * 25 + m];
            int prev = m ? off[b * 25 + m - 1] : 0;
            il = 1.0f / (float)(e - prev);
        }
        g_invlen[r] = il;
    }
}

__device__ void head_const_region(const float* __restrict__ bvec, const float* __restrict__ W,
                                  const float* __restrict__ bo, float* __restrict__ outp)
{
    int tid = threadIdx.x;  // 256
    float a0 = 0.f, a1 = 0.f;
#pragma unroll
    for (int hh = 0; hh < 4; hh++) {
        int idx = tid * 4 + hh;
        float x = tanhf(bvec[idx]);
        a0 = fmaf(x, W[idx * 2],     a0);
        a1 = fmaf(x, W[idx * 2 + 1], a1);
    }
#pragma unroll
    for (int o = 16; o > 0; o >>= 1) {
        a0 += __shfl_down_sync(0xffffffffu, a0, o);
        a1 += __shfl_down_sync(0xffffffffu, a1, o);
    }
    __shared__ float s0[8], s1[8];
    int wid = tid >> 5, lane = tid & 31;
    if (lane == 0) { s0[wid] = a0; s1[wid] = a1; }
    __syncthreads();
    if (tid == 0) {
        float t0 = 0.f, t1 = 0.f;
        for (int q = 0; q < 8; q++) { t0 += s0[q]; t1 += s1[q]; }
        outp[0] = t0 + bo[0];
        outp[1] = t1 + bo[1];
    }
}

__device__ void packB_region(int nb, int s, const float* __restrict__ Wa,
                             const float* __restrict__ Wb, int which,
                             __half* __restrict__ Bpack)
{
    __shared__ __align__(16) float ws[32][132];
    for (int e = threadIdx.x; e < 32 * 32; e += 256) {
        int k = e >> 5, n4 = (e & 31) << 2;
        int kg = s * 32 + k, ng = nb * 128 + n4;
        float4 v;
        if (which == 0) {
            v = (ng < 1024) ? ld4(Wa + (size_t)kg * 1024 + ng)
                            : ld4(Wb + (size_t)kg * 1024 + (ng - 1024));
        } else {
            if (ng < 1024) {
                v = ld4(Wa + (size_t)kg * 1024 + ng);
            } else if (ng < 2048) {
                int cc = ng - 1024;
                float4 a = ld4(Wb + (size_t)kg * 1024 + cc);
                float4 b = ld4(Wb + (size_t)(2048 + kg) * 1024 + cc);
                v = make_float4(a.x + b.x, a.y + b.y, a.z + b.z, a.w + b.w);
            } else {
                int cc = ng - 2048;
                float4 a = ld4(Wb + (size_t)(1024 + kg) * 1024 + cc);
                float4 b = ld4(Wb + (size_t)(2048 + kg) * 1024 + cc);
                v = make_float4(a.x - b.x, a.y - b.y, a.z - b.z, a.w - b.w);
            }
        }
        *(float4*)&ws[k][n4] = v;
    }
    __syncthreads();
    __half* tile = Bpack + ((size_t)(nb * 32 + s)) * 8192;
    for (int c = threadIdx.x; c < 512; c += 256) {
        int kk16 = c >> 8, nt16b = (c >> 5) & 7, lane = c & 31;
        int gq = lane >> 2, tg = lane & 3;
        int kl = kk16 * 16 + 2 * tg;
        int ne = nt16b * 16 + gq, no = ne + 8;
        uint4 hi, lo;
        hl2(ws[kl][ne],     ws[kl + 1][ne], hi.x, lo.x);
        hl2(ws[kl + 8][ne], ws[kl + 9][ne], hi.y, lo.y);
        hl2(ws[kl][no],     ws[kl + 1][no], hi.z, lo.z);
        hl2(ws[kl + 8][no], ws[kl + 9][no], hi.w, lo.w);
        uint32_t off = (uint32_t)(kk16 * 8 + nt16b) * 512 + lane * 16;
        *(uint4*)((char*)tile + off)        = hi;
        *(uint4*)((char*)tile + 8192 + off) = lo;
    }
}

__device__ void packAcls_region(int s, const float* __restrict__ seq)
{
    __half* tile = g_ApackC + ((size_t)s) * 8192;
    for (int c = threadIdx.x; c < 512; c += 256) {
        int kk16 = c >> 8, mt16 = (c >> 5) & 7, lane = c & 31;
        int gq = lane >> 2, tg = lane & 3;
        int kb = s * 32 + kk16 * 16 + 2 * tg;
        int r0 = mt16 * 16 + gq, r1 = r0 + 8;
        float x0[4] = {0, 0, 0, 0}, x1[4] = {0, 0, 0, 0};
        if (r0 < 64) { const float* p = seq + (size_t)r0 * 524288 + kb;
                       x0[0] = p[0]; x0[1] = p[1]; x0[2] = p[8]; x0[3] = p[9]; }
        if (r1 < 64) { const float* p = seq + (size_t)r1 * 524288 + kb;
                       x1[0] = p[0]; x1[1] = p[1]; x1[2] = p[8]; x1[3] = p[9]; }
        uint4 hi, lo;
        hl2(x0[0], x0[1], hi.x, lo.x);
        hl2(x1[0], x1[1], hi.y, lo.y);
        hl2(x0[2], x0[3], hi.z, lo.z);
        hl2(x1[2], x1[3], hi.w, lo.w);
        uint32_t off = (uint32_t)(kk16 * 8 + mt16) * 512 + lane * 16;
        *(uint4*)((char*)tile + off)        = hi;
        *(uint4*)((char*)tile + 8192 + off) = lo;
    }
}

// blocks: [0,416) zero | 416 prefix | [417,431) prep | [431,1199) packB3 |
//         [1199,1711) packB2 | [1711,1743) packAcls
__global__ __launch_bounds__(256) void K_front(
    const float* __restrict__ seq, const int* __restrict__ off,
    const float* __restrict__ W_naf, const float* __restrict__ b_naf,
    const float* __restrict__ W_cd,  const float* __restrict__ b_cd,
    const float* __restrict__ W_nd,  const float* __restrict__ b_nd,
    const float* __restrict__ W_ed,  const float* __restrict__ b_ed,
    const float* __restrict__ W_no,  const float* __restrict__ b_no,
    const float* __restrict__ W_eo,  const float* __restrict__ b_eo)
{
    int i = blockIdx.x;
    if (i < 416) {
        float4 z = {0.f, 0.f, 0.f, 0.f};
#pragma unroll
        for (int r = 0; r < 4; r++)
            *(float4*)(g_node + ((size_t)i * 4 + r) * 1024 + threadIdx.x * 4) = z;
    } else if (i == 416) {
        prefix_region(off);
    } else if (i < 431) {
        int blk = i - 417;
        if (blk < 12) {
            int t = blk * 256 + threadIdx.x;
            if (t < 2048) g_bcat2[t] = (t < 1024) ? b_naf[t] : b_cd[t - 1024];
            if (t < 3072) g_bcat3[t] = (t < 1024) ? b_nd[t] : ((t < 2048) ? b_ed[t - 1024] : 0.0f);
        } else if (blk == 12) {
            head_const_region(b_nd, W_no, b_no, g_zlog);
        } else {
            head_const_region(b_ed, W_eo, b_eo, g_elog);
        }
    } else if (i < 1199) {
        int j = i - 431;
        packB_region(j >> 5, j & 31, W_nd, W_ed, 1, g_BpackN);
    } else if (i < 1711) {
        int j = i - 1199;
        packB_region(j >> 5, j & 31, W_naf, W_cd, 0, g_BpackC);
    } else {
        packAcls_region(i - 1711, seq);
    }
}

// ---------------- segment accumulation: balanced 32-row chunks ----------------
__global__ __launch_bounds__(256) void seg_accum_kernel(const float* __restrict__ seq,
                                                        const int* __restrict__ off)
{
    int b = blockIdx.x, q = blockIdx.y;
    __shared__ int soff[25];
    __shared__ int segid[32];
    int tid = threadIdx.x;
    if (tid < 25) soff[tid] = off[b * 25 + tid];
    __syncthreads();
    int c = 0;
#pragma unroll
    for (int m = 0; m < 25; m++) c += (soff[m] > 0);
    if (tid < 32) {
        int s = q * 32 + tid;
        int id = -1;
        if (s >= 1 && s <= soff[c - 1]) {
#pragma unroll
            for (int m = 0; m < 25; m++) {
                if (s <= soff[m]) { id = m; break; }
            }
        }
        segid[tid] = id;
    }
    __syncthreads();

    const float* base = seq + ((size_t)b * 512 + q * 32) * 1024 + tid * 4;
    float4 acc = {0.f, 0.f, 0.f, 0.f};
    int cur = -1;
#pragma unroll
    for (int g = 0; g < 4; g++) {
        float4 v[8];
#pragma unroll
        for (int r = 0; r < 8; r++) {
            int rr = g * 8 + r;
            v[r] = (segid[rr] >= 0) ? *(const float4*)(base + (size_t)rr * 1024)
                                    : make_float4(0.f, 0.f, 0.f, 0.f);
        }
#pragma unroll
        for (int r = 0; r < 8; r++) {
            int rr = g * 8 + r;
            int id = segid[rr];
            if (id != cur) {
                if (cur >= 0) {
                    float* d = g_node + ((size_t)(b * 26 + cur)) * 1024 + tid * 4;
                    atomicAdd(d + 0, acc.x); atomicAdd(d + 1, acc.y);
                    atomicAdd(d + 2, acc.z); atomicAdd(d + 3, acc.w);
                }
                acc = make_float4(0.f, 0.f, 0.f, 0.f);
                cur = id;
            }
            if (id >= 0) { acc.x += v[r].x; acc.y += v[r].y; acc.z += v[r].z; acc.w += v[r].w; }
        }
    }
    if (cur >= 0) {
        float* d = g_node + ((size_t)(b * 26 + cur)) * 1024 + tid * 4;
        atomicAdd(d + 0, acc.x); atomicAdd(d + 1, acc.y);
        atomicAdd(d + 2, acc.z); atomicAdd(d + 3, acc.w);
    }
}

// ---------------- A pack (node, normalization folded) ----------------
__global__ void packAnode_kernel()
{
    int mb = blockIdx.x, s = blockIdx.y;
    int R = g_R;
    if (mb * 128 >= R) return;
    __half* tile = g_ApackN + ((size_t)(mb * 32 + s)) * 8192;
    for (int c = threadIdx.x; c < 512; c += 256) {
        int kk16 = c >> 8, mt16 = (c >> 5) & 7, lane = c & 31;
        int gq = lane >> 2, tg = lane & 3;
        int kb = s * 32 + kk16 * 16 + 2 * tg;
        int r0 = mb * 128 + mt16 * 16 + gq, r1 = r0 + 8;
        float x0[4] = {0, 0, 0, 0}, x1[4] = {0, 0, 0, 0};
        if (r0 < R) {
            int src = g_rowmap[r0];
            float il = g_invlen[src];
            const float* p = g_node + (size_t)src * 1024 + kb;
            x0[0] = p[0] * il; x0[1] = p[1] * il; x0[2] = p[8] * il; x0[3] = p[9] * il;
        }
        if (r1 < R) {
            int src = g_rowmap[r1];
            float il = g_invlen[src];
            const float* p = g_node + (size_t)src * 1024 + kb;
            x1[0] = p[0] * il; x1[1] = p[1] * il; x1[2] = p[8] * il; x1[3] = p[9] * il;
        }
        uint4 hi, lo;
        hl2(x0[0], x0[1], hi.x, lo.x);
        hl2(x1[0], x1[1], hi.y, lo.y);
        hl2(x0[2], x0[3], hi.z, lo.z);
        hl2(x1[2], x1[3], hi.w, lo.w);
        uint32_t off = (uint32_t)(kk16 * 8 + mt16) * 512 + lane * 16;
        *(uint4*)((char*)tile + off)        = hi;
        *(uint4*)((char*)tile + 8192 + off) = lo;
    }
}

// ---------------- fp16 3-term GEMM, block 64x128, BK=32, 3-stage pipeline ----------------
// stage: A 8KB (hi|lo) ++ B 16KB (hi|lo) = 24KB; 3 stages = 72KB
#define STAGE 24576
__global__ __launch_bounds__(256) void gemm3_kernel(
    const __half* __restrict__ Apack, const __half* __restrict__ Bpack,
    const float* __restrict__ bias, float* __restrict__ C, int ldc,
    const int* __restrict__ Mptr, int tanh_lo, int tanh_hi, int mode)
{
    int R = *Mptr;
    int mb = blockIdx.x, nb = blockIdx.y;
    if (mb * 64 >= R) return;
    int mb128 = mb >> 1, mhalf4 = (mb & 1) * 4;
    extern __shared__ char sm[];
    uint32_t sb = smem_u32(sm);
    int tid = threadIdx.x, lane = tid & 31, w = tid >> 5;
    int gq = lane >> 2, tg = lane & 3;
    int wmt = (w & 1) * 2;
    int wnb = (w >> 1) * 2;

    const char* Ab = (const char*)Apack + (size_t)(mb128 * 32) * 16384;
    const char* Bb = (const char*)Bpack + (size_t)(nb * 32) * 16384;

    uint32_t aoff = (uint32_t)((tid >> 7) * 8 + mhalf4 + ((tid >> 5) & 3)) * 512 + (tid & 31) * 16;

    float    acc [2][4][4];
    uint32_t accH[2][4][2];
#pragma unroll
    for (int mt = 0; mt < 2; mt++)
#pragma unroll
        for (int nt = 0; nt < 4; nt++) {
#pragma unroll
            for (int q = 0; q < 4; q++) acc[mt][nt][q] = 0.f;
            accH[mt][nt][0] = 0u; accH[mt][nt][1] = 0u;
        }

#define COPY_STAGE(dstb, s_) do { \
    const char* As_ = Ab + (size_t)(s_) * 16384; \
    const char* Bs_ = Bb + (size_t)(s_) * 16384; \
    CP16((dstb) + tid * 16,          As_ + aoff); \
    CP16((dstb) + 4096 + tid * 16,   As_ + 8192 + aoff); \
    CP16((dstb) + 8192  + tid * 16,  Bs_ + tid * 16); \
    CP16((dstb) + 12288 + tid * 16,  Bs_ + 4096 + tid * 16); \
    CP16((dstb) + 16384 + tid * 16,  Bs_ + 8192 + tid * 16); \
    CP16((dstb) + 20480 + tid * 16,  Bs_ + 12288 + tid * 16); \
    CP_COMMIT(); \
} while (0)

    COPY_STAGE(sb, 0);
    COPY_STAGE(sb + STAGE, 1);

    int bufn = 2;   // buffer index of next copy
    for (int s = 0; s < 32; s++) {
        if (s < 30) {
            COPY_STAGE(sb + bufn * STAGE, s + 2);
            bufn = (bufn == 2) ? 0 : bufn + 1;
            CP_WAIT2();
        } else if (s == 30) {
            CP_WAIT1();
        } else {
            CP_WAIT0();
        }
        __syncthreads();
        int bufc = s - (s / 3) * 3;
        const char* st = sm + bufc * STAGE;
#pragma unroll
        for (int kk = 0; kk < 2; kk++) {
            uint4 Ah[2], Al[2];
#pragma unroll
            for (int mt = 0; mt < 2; mt++) {
                uint32_t ao = (uint32_t)(kk * 4 + wmt + mt) * 512 + lane * 16;
                Ah[mt] = *(const uint4*)(st + ao);
                Al[mt] = *(const uint4*)(st + 4096 + ao);
            }
#pragma unroll
            for (int ntb = 0; ntb < 2; ntb++) {
                uint32_t bo = (uint32_t)(kk * 8 + wnb + ntb) * 512 + lane * 16;
                uint4 bh = *(const uint4*)(st + 8192 + bo);
                uint4 bl = *(const uint4*)(st + 16384 + bo);
#pragma unroll
                for (int mt = 0; mt < 2; mt++) {
                    MMA16 (acc [mt][2 * ntb],     Ah[mt], bh.x, bh.y);
                    MMA16H(accH[mt][2 * ntb],     Al[mt], bh.x, bh.y);
                    MMA16H(accH[mt][2 * ntb],     Ah[mt], bl.x, bl.y);
                    MMA16 (acc [mt][2 * ntb + 1], Ah[mt], bh.z, bh.w);
                    MMA16H(accH[mt][2 * ntb + 1], Al[mt], bh.z, bh.w);
                    MMA16H(accH[mt][2 * ntb + 1], Ah[mt], bl.z, bl.w);
                }
            }
        }
        __syncthreads();
    }

#pragma unroll
    for (int nt = 0; nt < 4; nt++) {
        int col = nb * 128 + (w >> 1) * 32 + nt * 8 + 2 * tg;
        float b0 = bias[col], b1 = bias[col + 1];
        bool dt = (col >= tanh_lo) && (col < tanh_hi);
#pragma unroll
        for (int mt = 0; mt < 2; mt++) {
            int row = mb * 64 + (w & 1) * 32 + mt * 16 + gq;
            __half2 h01 = *(__half2*)&accH[mt][nt][0];
            __half2 h23 = *(__half2*)&accH[mt][nt][1];
            float v0 = acc[mt][nt][0] + __low2float(h01)  + b0;
            float v1 = acc[mt][nt][1] + __high2float(h01) + b1;
            float v2 = acc[mt][nt][2] + __low2float(h23)  + b0;
            float v3 = acc[mt][nt][3] + __high2float(h23) + b1;
            if (dt) { v0 = ftanh(v0); v1 = ftanh(v1); v2 = ftanh(v2); v3 = ftanh(v3); }
            if (mode == 1) {
                // G1: rows < 64 always valid. cols<1024 -> naf scattered into g_node;
                // cols>=1024 -> tanh'd, to g_C2.
                int row1 = row + 8;
                if (col < 1024) {
                    int c0 = g_count[row], c1 = g_count[row1];
                    float2 p0 = {v0, v1};
                    *(float2*)(g_node + ((size_t)(row  * 26 + c0)) * 1024 + col) = p0;
                    float2 p1 = {v2, v3};
                    *(float2*)(g_node + ((size_t)(row1 * 26 + c1)) * 1024 + col) = p1;
                } else {
                    float2 p0 = {v0, v1};
                    *(float2*)(g_C2 + (size_t)row  * 2048 + col) = p0;
                    float2 p1 = {v2, v3};
                    *(float2*)(g_C2 + (size_t)row1 * 2048 + col) = p1;
                }
            } else {
                if (row < R)     { float2 p = {v0, v1}; *(float2*)(C + (size_t)row * ldc + col) = p; }
                if (row + 8 < R) { float2 p = {v2, v3}; *(float2*)(C + (size_t)(row + 8) * ldc + col) = p; }
            }
        }
    }
}

// ---------------- K_tail: logits | node_logits | edge_logits ----------------
__global__ __launch_bounds__(128) void K_tail(
    const float* __restrict__ W_co, const float* __restrict__ b_co,
    const float* __restrict__ W_no, const float* __restrict__ b_no,
    const float* __restrict__ W_eo, const float* __restrict__ b_eo,
    float* __restrict__ out)
{
    int blk = blockIdx.x, tid = threadIdx.x;
    const float* x; const float* Wv; const float* bs; float* op;
    float xs[8];

    if (blk < 1728) {
        if (blk < 64) {
            x  = g_C2 + (size_t)blk * 2048 + 1024;
            Wv = W_co; bs = b_co; op = out + blk * 2;
        } else {
            int r = blk - 64;
            int b = r / 26, m = r - b * 26;
            op = out + 128 + r * 2;
            if (m > g_count[b]) {
                if (tid == 0) { op[0] = g_zlog[0]; op[1] = g_zlog[1]; }
                return;
            }
            x  = g_Cbig + (size_t)(g_pref[b] + m) * 3072;
            Wv = W_no; bs = b_no;
        }
        const float4* xv = (const float4*)(x + tid * 8);
        *(float4*)xs       = xv[0];
        *(float4*)(xs + 4) = xv[1];
    } else {
        int ke = blk - 1728;
        int b  = ke / 676;
        int k  = ke - b * 676;
        int n  = g_count[b] + 1;
        op = out + 3456 + (size_t)ke * 2;
        if (k >= n * n) {
            if (tid == 0) { op[0] = g_elog[0]; op[1] = g_elog[1]; }
            return;
        }
        int i = k / n, j = k - i * n;
        int pj = g_pref[b] + j, pi = g_pref[b] + i;
        const float* U = g_Cbig + (size_t)pj * 3072 + 1024 + tid * 8;
        const float* V = g_Cbig + (size_t)pi * 3072 + 2048 + tid * 8;
        float us[8], vs[8];
        *(float4*)us       = ((const float4*)U)[0];
        *(float4*)(us + 4) = ((const float4*)U)[1];
        *(float4*)vs       = ((const float4*)V)[0];
        *(float4*)(vs + 4) = ((const float4*)V)[1];
#pragma unroll
        for (int hh = 0; hh < 8; hh++) xs[hh] = ftanh(us[hh] + vs[hh]);
        Wv = W_eo; bs = b_eo;
    }

    float ws[16];
    {
        const float4* wv = (const float4*)(Wv + tid * 16);
#pragma unroll
        for (int q = 0; q < 4; q++) *(float4*)(ws + q * 4) = wv[q];
    }
    float a0 = 0.f, a1 = 0.f;
#pragma unroll
    for (int hh = 0; hh < 8; hh++) {
        a0 = fmaf(xs[hh], ws[2 * hh], a0);
        a1 = fmaf(xs[hh], ws[2 * hh + 1], a1);
    }
#pragma unroll
    for (int o = 16; o > 0; o >>= 1) {
        a0 += __shfl_down_sync(0xffffffffu, a0, o);
        a1 += __shfl_down_sync(0xffffffffu, a1, o);
    }
    __shared__ float s0[4], s1[4];
    int wid = tid >> 5, lane = tid & 31;
    if (lane == 0) { s0[wid] = a0; s1[wid] = a1; }
    __syncthreads();
    if (tid == 0) {
        op[0] = s0[0] + s0[1] + s0[2] + s0[3] + bs[0];
        op[1] = s1[0] + s1[1] + s1[2] + s1[3] + bs[1];
    }
}

// ---------------- launch ----------------
extern "C" void kernel_launch(void* const* d_in, const int* in_sizes, int n_in,
                              void* d_out, int out_size)
{
    const float* seq   = (const float*)d_in[0];
    const int*   off   = (const int*)d_in[1];
    const float* W_naf = (const float*)d_in[4];
    const float* b_naf = (const float*)d_in[5];
    const float* W_cd  = (const float*)d_in[6];
    const float* b_cd  = (const float*)d_in[7];
    const float* W_co  = (const float*)d_in[8];
    const float* b_co  = (const float*)d_in[9];
    const float* W_nd  = (const float*)d_in[10];
    const float* b_nd  = (const float*)d_in[11];
    const float* W_no  = (const float*)d_in[12];
    const float* b_no  = (const float*)d_in[13];
    const float* W_ed  = (const float*)d_in[14];
    const float* b_ed  = (const float*)d_in[15];
    const float* W_eo  = (const float*)d_in[16];
    const float* b_eo  = (const float*)d_in[17];
    float* out = (float*)d_out;

    float *pbcat2, *pbcat3, *pC2, *pCbig;
    __half *pApN, *pApC, *pBpN, *pBpC;
    int *pR, *pM1;
    cudaGetSymbolAddress((void**)&pbcat2, g_bcat2);
    cudaGetSymbolAddress((void**)&pbcat3, g_bcat3);
    cudaGetSymbolAddress((void**)&pC2,    g_C2);
    cudaGetSymbolAddress((void**)&pCbig,  g_Cbig);
    cudaGetSymbolAddress((void**)&pApN,   g_ApackN);
    cudaGetSymbolAddress((void**)&pApC,   g_ApackC);
    cudaGetSymbolAddress((void**)&pBpN,   g_BpackN);
    cudaGetSymbolAddress((void**)&pBpC,   g_BpackC);
    cudaGetSymbolAddress((void**)&pR,     g_R);
    cudaGetSymbolAddress((void**)&pM1,    g_M1);

    cudaFuncSetAttribute(gemm3_kernel, cudaFuncAttributeMaxDynamicSharedMemorySize, 3 * STAGE);

    // 1. front: zero | prefix | prep | packB3 | packB2 | packAcls
    K_front<<<1743, 256>>>(seq, off, W_naf, b_naf, W_cd, b_cd, W_nd, b_nd,
                           W_ed, b_ed, W_no, b_no, W_eo, b_eo);
    // 2. segment sums
    seg_accum_kernel<<<dim3(64, 16), 256>>>(seq, off);
    // 3. G1: cls @ [W_naf|W_cd]; naf -> g_node rows, tanh half -> g_C2
    gemm3_kernel<<<dim3(1, 16), 256, 3 * STAGE>>>(pApC, pBpC, pbcat2, pC2, 2048, pM1, 1024, 2048, 1);
    // 4. pack node A (normalization folded)
    packAnode_kernel<<<dim3(13, 32), 256>>>();
    // 5. G2: nodeC @ [W_nd|W1+W3|W2-W3] -> g_Cbig (tanh cols<1024)
    gemm3_kernel<<<dim3(26, 24), 256, 3 * STAGE>>>(pApN, pBpN, pbcat3, pCbig, 3072, pR, 0, 1024, 0);
    // 6. tail: logits | node_logits | edge_logits
    K_tail<<<64 + 1664 + 64 * 676, 128>>>(W_co, b_co, W_no, b_no, W_eo, b_eo, out);
}